// round 6
// baseline (speedup 1.0000x reference)
#include <cuda_runtime.h>
#include <math.h>
#include <stdint.h>

#define NSAMP 32768
#define FF 8
#define HU 128
#define VV 2048
#define LL 32
#define EE 1024
#define EPSB 1e-5f
#define DTT (1.0f/51360.0f)
#define SIGLEN 584
#define FINALW 9344
#define NSEG 129

typedef unsigned long long u64;

// ---- packed f32x2 helpers (Blackwell) ----
#define FMA2(d, a, b, c) asm("fma.rn.f32x2 %0, %1, %2, %3;" : "=l"(d) : "l"(a), "l"(b), "l"(c))
#define ADD2(d, a, b)    asm("add.rn.f32x2 %0, %1, %2;" : "=l"(d) : "l"(a), "l"(b))
#define PACKDUPF(out, f) asm("mov.b64 %0, {%1, %1};" : "=l"(out) : "f"(f))
#define UNPACKF(lo, hi, v) asm("mov.b64 {%0, %1}, %2;" : "=f"(lo), "=f"(hi) : "l"(v))

// ------------------------- scratch (__device__ globals) -------------------------
__device__ float g_bufA[(size_t)FF*NSAMP*HU];   // activated layer-2 outputs a2
__device__ float g_bufB[(size_t)FF*NSAMP*HU];   // layer-3 preacts
__device__ float g_yout[FF*NSAMP];
__device__ float g_cA[FF*HU], g_cB[FF*HU];
__device__ float g_scl3[FF*HU], g_shf3[FF*HU];
__device__ float g_sclO[FF], g_shfO[FF];
__device__ float g_partF[(size_t)FF*256*2*128];
__device__ double g_partO[FF*64*2];
__device__ float g_fv[(size_t)LL*FF*VV];
__device__ float g_x[LL*FINALW];
// piecewise-linear layer-2 machinery
__device__ float g_T[FF][HU];                   // sorted knots
__device__ float g_P[FF][NSEG][HU], g_Q[FF][NSEG][HU];      // Y2 = P*x+Q per segment
__device__ float g_PP[FF][NSEG][HU], g_QQ[FF][NSEG][HU];    // a2 = relu(PP*x+QQ)
__device__ int   g_seg[FF*NSAMP];
__device__ double g_sC[FF][16][NSEG], g_sX[FF][16][NSEG], g_sXX[FF][16][NSEG];

// --------------- x batch stats + analytic layer-1 BN coefficients ---------------
__global__ void k_xstats(const float* __restrict__ x, const float* __restrict__ Win,
                         const float* __restrict__ gin, const float* __restrict__ betain) {
    __shared__ double rs[1024], rq[1024];
    __shared__ double sm[2];
    int t = threadIdx.x;
    double s = 0.0, q = 0.0;
    for (int i = t; i < NSAMP; i += 1024) { double v = x[i]; s += v; q += v*v; }
    rs[t] = s; rq[t] = q; __syncthreads();
    for (int o = 512; o > 0; o >>= 1) {
        if (t < o) { rs[t] += rs[t+o]; rq[t] += rq[t+o]; }
        __syncthreads();
    }
    if (t == 0) { double mx = rs[0]/(double)NSAMP; sm[0] = mx; sm[1] = rq[0]/(double)NSAMP - mx*mx; }
    __syncthreads();
    double mx = sm[0], vx = sm[1];
    double w  = Win[t];
    double g  = gin[t];
    double be = betain[t];
    double cA = w * g / sqrt(w*w*vx + (double)EPSB);
    g_cA[t] = (float)cA;
    g_cB[t] = (float)(be - cA*mx);
}

// ---------------- build sorted knots + per-segment (P,Q) via prefix scan --------
__global__ void __launch_bounds__(128) k_build1(const float* __restrict__ Wh) {
    int f = blockIdx.x, tid = threadIdx.x;
    __shared__ float sT[128], s_cA[128], s_cB[128];
    __shared__ int sK[128];
    __shared__ unsigned char s_init[128];
    float ca = g_cA[f*HU + tid], cb = g_cB[f*HU + tid];
    s_cA[tid] = ca; s_cB[tid] = cb;
    float t;
    if (ca == 0.f) t = __int_as_float(0x7f800000);   // +inf, never crossed
    else t = -cb/ca;
    sT[tid] = t; sK[tid] = tid;
    s_init[tid] = (ca < 0.f) || (ca == 0.f && cb > 0.f);
    __syncthreads();
    // bitonic sort (t,k) ascending
    for (int k = 2; k <= 128; k <<= 1) {
        for (int j = k >> 1; j > 0; j >>= 1) {
            int ixj = tid ^ j;
            if (ixj > tid) {
                float a = sT[tid], b = sT[ixj];
                bool up = ((tid & k) == 0);
                if ((a > b) == up) {
                    sT[tid] = b; sT[ixj] = a;
                    int ka = sK[tid]; sK[tid] = sK[ixj]; sK[ixj] = ka;
                }
            }
            __syncthreads();
        }
    }
    g_T[f][tid] = sT[tid];
    const float* W = Wh + (size_t)f*2*HU*HU;   // hidden layer 0 weights [j][k]
    // initial active set (segment 0)
    float p = 0.f, q = 0.f;
    for (int k = 0; k < 128; k++) {
        if (s_init[k]) {
            float w = W[tid*HU + k];
            p = fmaf(w, s_cA[k], p);
            q = fmaf(w, s_cB[k], q);
        }
    }
    g_P[f][0][tid] = p; g_Q[f][0][tid] = q;
    for (int s = 1; s < NSEG; s++) {
        int ks = sK[s-1];
        float cka = s_cA[ks];
        if (cka != 0.f) {
            float w = W[tid*HU + ks];
            float sgn = (cka > 0.f) ? 1.f : -1.f;
            p = fmaf(sgn*w, cka, p);
            q = fmaf(sgn*w, s_cB[ks], q);
        }
        g_P[f][s][tid] = p; g_Q[f][s][tid] = q;
    }
}

// ---------------------------- segment id per sample -----------------------------
__global__ void __launch_bounds__(256) k_seg(const float* __restrict__ x) {
    int f = blockIdx.y;
    __shared__ float sT[128];
    if (threadIdx.x < 128) sT[threadIdx.x] = g_T[f][threadIdx.x];
    __syncthreads();
    int n = blockIdx.x*256 + threadIdx.x;
    float xv = x[n];
    int lo = 0, hi = 128;
    #pragma unroll
    for (int it = 0; it < 7; it++) {
        int mid = (lo + hi) >> 1;
        if (sT[mid] < xv) lo = mid + 1; else hi = mid;
    }
    if (lo < hi && sT[lo] < xv) lo++;
    g_seg[f*NSAMP + n] = lo;
}

// ------------------ deterministic per-segment (cnt, Sx, Sxx) --------------------
__global__ void __launch_bounds__(256) k_segstats(const float* __restrict__ x) {
    int f = blockIdx.y, ch = blockIdx.x;
    __shared__ float sx[2048];
    __shared__ short ss[2048];
    int n0 = ch*2048;
    for (int i = threadIdx.x; i < 2048; i += 256) {
        sx[i] = x[n0 + i];
        ss[i] = (short)g_seg[f*NSAMP + n0 + i];
    }
    __syncthreads();
    int b = threadIdx.x;
    if (b < NSEG) {
        double c = 0.0, s = 0.0, q = 0.0;
        for (int i = 0; i < 2048; i++) {
            if (ss[i] == b) { double v = sx[i]; c += 1.0; s += v; q += v*v; }
        }
        g_sC[f][ch][b] = c; g_sX[f][ch][b] = s; g_sXX[f][ch][b] = q;
    }
}

// --------- layer-2 BN coefs from segment aggregates + fused PP/QQ tables --------
__global__ void __launch_bounds__(128) k_bncoef2(const float* __restrict__ gh,
                                                 const float* __restrict__ betah) {
    int f = blockIdx.x, j = threadIdx.x;
    __shared__ double shC[NSEG], shX[NSEG], shXX[NSEG];
    // FIX: strided fill — 129 bins, 128 threads (bin 128 was garbage before)
    for (int jj = j; jj < NSEG; jj += 128) {
        double c = 0.0, s = 0.0, q = 0.0;
        for (int ch = 0; ch < 16; ch++) {
            c += g_sC[f][ch][jj]; s += g_sX[f][ch][jj]; q += g_sXX[f][ch][jj];
        }
        shC[jj] = c; shX[jj] = s; shXX[jj] = q;
    }
    __syncthreads();
    double S = 0.0, Q2 = 0.0;
    for (int s = 0; s < NSEG; s++) {
        double p = g_P[f][s][j], q = g_Q[f][s][j];
        S  += p*shX[s] + q*shC[s];
        Q2 += p*p*shXX[s] + 2.0*p*q*shX[s] + q*q*shC[s];
    }
    double mean = S/(double)NSAMP;
    double var  = Q2/(double)NSAMP - mean*mean;
    double g  = gh[f*2*HU + j];          // hidden layer 0 BN params
    double be = betah[f*2*HU + j];
    double scl = g / sqrt(var + (double)EPSB);
    double shf = be - scl*mean;
    for (int s = 0; s < NSEG; s++) {
        float p = g_P[f][s][j], q = g_Q[f][s][j];
        g_PP[f][s][j] = (float)(scl*(double)p);
        g_QQ[f][s][j] = (float)(scl*(double)q + shf);
    }
}

// ------------- materialize a2[f][n][k] = relu(PP[s_n][k]*x_n + QQ) --------------
__global__ void __launch_bounds__(256) k_a2(const float* __restrict__ x) {
    int f = blockIdx.y;
    int k = threadIdx.x & 127, half = threadIdx.x >> 7;
    int n0 = blockIdx.x*128;
    __shared__ float sx[128];
    __shared__ short ss[128];
    if (threadIdx.x < 128) {
        sx[threadIdx.x] = x[n0 + threadIdx.x];
        ss[threadIdx.x] = (short)g_seg[f*NSAMP + n0 + threadIdx.x];
    }
    __syncthreads();
    for (int i = half; i < 128; i += 2) {
        int s = ss[i];
        float a = fmaf(g_PP[f][s][k], sx[i], g_QQ[f][s][k]);
        g_bufA[((size_t)f*NSAMP + n0 + i)*HU + k] = fmaxf(a, 0.f);
    }
}

// --------------------------- hidden-layer GEMM (f32x2) --------------------------
__global__ void __launch_bounds__(256, 2) k_gemm(const float* __restrict__ Wh) {
    __shared__ __align__(16) float As[32][132];
    __shared__ __align__(16) float Bs[32][132];

    int f = blockIdx.y, bx = blockIdx.x, m0 = bx * 128, tid = threadIdx.x;
    int tx = tid & 15, ty = tid >> 4;

    const float* W = Wh + ((size_t)f*2 + 1)*HU*HU;

    u64 acc[8][4];
    #pragma unroll
    for (int r = 0; r < 8; r++)
        #pragma unroll
        for (int c = 0; c < 4; c++) acc[r][c] = 0ull;

    for (int k0 = 0; k0 < HU; k0 += 32) {
        #pragma unroll
        for (int i = 0; i < 16; i++) {
            int idx = tid + i*256;
            int kk = idx & 31, n = idx >> 5;
            As[kk][n] = g_bufA[((size_t)f*NSAMP + m0 + n)*HU + k0 + kk];
            Bs[kk][n] = W[n*HU + k0 + kk];
        }
        __syncthreads();
        #pragma unroll
        for (int kk = 0; kk < 32; kk++) {
            float a[8];
            *(float4*)(a)   = *(const float4*)&As[kk][ty*8];
            *(float4*)(a+4) = *(const float4*)&As[kk][ty*8+4];
            u64 b[4];
            *(ulonglong2*)(b)   = *(const ulonglong2*)&Bs[kk][tx*8];
            *(ulonglong2*)(b+2) = *(const ulonglong2*)&Bs[kk][tx*8+4];
            #pragma unroll
            for (int r = 0; r < 8; r++) {
                u64 a2;
                PACKDUPF(a2, a[r]);
                #pragma unroll
                for (int c = 0; c < 4; c++) FMA2(acc[r][c], a2, b[c], acc[r][c]);
            }
        }
        __syncthreads();
    }

    #pragma unroll
    for (int r = 0; r < 8; r++) {
        size_t base = ((size_t)f*NSAMP + m0 + ty*8 + r)*HU + tx*8;
        ulonglong2 v0; v0.x = acc[r][0]; v0.y = acc[r][1];
        ulonglong2 v1; v1.x = acc[r][2]; v1.y = acc[r][3];
        *(ulonglong2*)&g_bufB[base]   = v0;
        *(ulonglong2*)&g_bufB[base+4] = v1;
    }

    u64 s2[4], q2[4];
    #pragma unroll
    for (int c = 0; c < 4; c++) { s2[c] = 0ull; q2[c] = 0ull; }
    #pragma unroll
    for (int r = 0; r < 8; r++)
        #pragma unroll
        for (int c = 0; c < 4; c++) {
            ADD2(s2[c], s2[c], acc[r][c]);
            FMA2(q2[c], acc[r][c], acc[r][c], q2[c]);
        }
    __syncthreads();
    u64* sh = (u64*)&As[0][0];
    #pragma unroll
    for (int c = 0; c < 4; c++) {
        sh[(ty*16 + tx)*4 + c]        = s2[c];
        sh[1024 + (ty*16 + tx)*4 + c] = q2[c];
    }
    __syncthreads();
    if (tid < 64) {
        int txx = tid >> 2, cpi = tid & 3;
        u64 S = 0ull, Q = 0ull;
        #pragma unroll
        for (int t2 = 0; t2 < 16; t2++) {
            ADD2(S, S, sh[(t2*16 + txx)*4 + cpi]);
            ADD2(Q, Q, sh[1024 + (t2*16 + txx)*4 + cpi]);
        }
        float slo, shi, qlo, qhi;
        UNPACKF(slo, shi, S);
        UNPACKF(qlo, qhi, Q);
        int col = txx*8 + cpi*2;
        float* P = g_partF + (((size_t)f*256 + bx)*2)*128;
        P[col] = slo; P[col+1] = shi;
        P[128+col] = qlo; P[128+col+1] = qhi;
    }
}

// --------------------- BN coefficients from GEMM partials -----------------------
__global__ void k_bncoef3(const float* __restrict__ gh, const float* __restrict__ betah) {
    int f = blockIdx.x;
    int u = threadIdx.x & 127, h = threadIdx.x >> 7;
    double S = 0.0, Q = 0.0;
    #pragma unroll 8
    for (int b = h; b < 256; b += 8) {
        const float* P = g_partF + (((size_t)f*256 + b)*2)*128;
        S += P[u]; Q += P[128+u];
    }
    __shared__ double shS[1024], shQ[1024];
    shS[h*128+u] = S; shQ[h*128+u] = Q;
    __syncthreads();
    if (h == 0) {
        #pragma unroll
        for (int i = 1; i < 8; i++) { S += shS[i*128+u]; Q += shQ[i*128+u]; }
        double mean = S/(double)NSAMP;
        double var  = Q/(double)NSAMP - mean*mean;
        double g  = gh[f*2*HU + HU + u];
        double be = betah[f*2*HU + HU + u];
        double scl = g / sqrt(var + (double)EPSB);
        g_scl3[f*HU+u] = (float)scl;
        g_shf3[f*HU+u] = (float)(be - scl*mean);
    }
}

// ---------------------- output layer: dot + stats -------------------------------
__global__ void __launch_bounds__(256) k_out(const float* __restrict__ Wout) {
    int f = blockIdx.y;
    int w = threadIdx.x >> 5, lane = threadIdx.x & 31;
    __shared__ float s_w[HU], s_scl[HU], s_shf[HU];
    if (threadIdx.x < 128) {
        s_w[threadIdx.x]   = Wout[f*HU + threadIdx.x];
        s_scl[threadIdx.x] = g_scl3[f*HU + threadIdx.x];
        s_shf[threadIdx.x] = g_shf3[f*HU + threadIdx.x];
    }
    __syncthreads();
    int wg = blockIdx.x*8 + w;
    int n0 = wg*64;
    float w0 = s_w[lane*4], w1 = s_w[lane*4+1], w2 = s_w[lane*4+2], w3 = s_w[lane*4+3];
    float c0 = s_scl[lane*4], c1 = s_scl[lane*4+1], c2 = s_scl[lane*4+2], c3 = s_scl[lane*4+3];
    float h0 = s_shf[lane*4], h1 = s_shf[lane*4+1], h2 = s_shf[lane*4+2], h3 = s_shf[lane*4+3];
    double s = 0.0, q = 0.0;
    for (int n = n0; n < n0 + 64; n++) {
        float4 y = *(const float4*)&g_bufB[((size_t)f*NSAMP + n)*HU + lane*4];
        float p = fmaxf(fmaf(y.x, c0, h0), 0.f)*w0 + fmaxf(fmaf(y.y, c1, h1), 0.f)*w1
                + fmaxf(fmaf(y.z, c2, h2), 0.f)*w2 + fmaxf(fmaf(y.w, c3, h3), 0.f)*w3;
        #pragma unroll
        for (int o = 16; o > 0; o >>= 1) p += __shfl_down_sync(0xffffffffu, p, o);
        if (lane == 0) { g_yout[f*NSAMP + n] = p; s += p; q += (double)p*p; }
    }
    __shared__ double sh_s[8], sh_q[8];
    if (lane == 0) { sh_s[w] = s; sh_q[w] = q; }
    __syncthreads();
    if (threadIdx.x == 0) {
        double S = 0.0, Q = 0.0;
        for (int i = 0; i < 8; i++) { S += sh_s[i]; Q += sh_q[i]; }
        g_partO[(f*64 + blockIdx.x)*2 + 0] = S;
        g_partO[(f*64 + blockIdx.x)*2 + 1] = Q;
    }
}

__global__ void k_bnO(const float* __restrict__ gout, const float* __restrict__ betaout) {
    int f = threadIdx.x;
    if (f >= FF) return;
    double S = 0.0, Q = 0.0;
    for (int b = 0; b < 64; b++) { S += g_partO[(f*64+b)*2]; Q += g_partO[(f*64+b)*2+1]; }
    double mean = S/(double)NSAMP;
    double var  = Q/(double)NSAMP - mean*mean;
    double scl = (double)gout[f] / sqrt(var + (double)EPSB);
    g_sclO[f] = (float)scl;
    g_shfO[f] = (float)((double)betaout[f] - scl*mean);
}

// ---------------------- einsum: fv[l][f][v] = sum_e evs * eigvec ----------------
__global__ void __launch_bounds__(256) k_einsum(const float* __restrict__ eigvec) {
    int l = blockIdx.y;
    int v0 = blockIdx.x*512 + threadIdx.x*2;
    __shared__ float evs[FF][EE];
    for (int idx = threadIdx.x; idx < FF*EE; idx += 256) {
        int f = idx >> 10, e = idx & 1023;
        float y = g_yout[f*NSAMP + l*EE + e];
        evs[f][e] = fmaxf(fmaf(y, g_sclO[f], g_shfO[f]), 0.f);
    }
    __syncthreads();
    float2 acc[FF];
    #pragma unroll
    for (int f = 0; f < FF; f++) acc[f] = make_float2(0.f, 0.f);
    const float* base = eigvec + ((size_t)l*EE)*VV + v0;
    #pragma unroll 4
    for (int e = 0; e < EE; e++) {
        float2 wv = *(const float2*)(base + (size_t)e*VV);
        #pragma unroll
        for (int f = 0; f < FF; f++) {
            float ev = evs[f][e];
            acc[f].x = fmaf(ev, wv.x, acc[f].x);
            acc[f].y = fmaf(ev, wv.y, acc[f].y);
        }
    }
    #pragma unroll
    for (int f = 0; f < FF; f++)
        *(float2*)&g_fv[((size_t)l*FF + f)*VV + v0] = acc[f];
}

// -------------------- gather + project + sort + level-3 signature ---------------
__global__ void __launch_bounds__(256) k_sig(const int* __restrict__ dgm0,
                                             const int* __restrict__ dgm1rel,
                                             const int* __restrict__ dgm1ext,
                                             const float* __restrict__ Wp,
                                             const float* __restrict__ bp) {
    int bid = blockIdx.x;
    int which = bid & 1;
    int row = bid >> 1;
    int tid = threadIdx.x;
    __shared__ float vals[640];
    __shared__ float srows[7*512];
    __shared__ float s_w0[7], s_w1[7], s_b[7];
    const float* fvr = g_fv + (size_t)row*VV;
    if (tid < 7) { s_w0[tid] = Wp[tid*2]; s_w1[tid] = Wp[tid*2+1]; s_b[tid] = bp[tid]; }
    for (int t = tid; t < 640; t += 256) {
        int src;
        if (which)        src = dgm1ext[row*640 + t];
        else if (t < 512) src = dgm0[row*512 + t];
        else              src = dgm1rel[row*129 + (128 - (t - 512))];
        vals[t] = fvr[src];
    }
    __syncthreads();
    const float PINF = __int_as_float(0x7f800000);
    for (int idx = tid; idx < 7*512; idx += 256) {
        int s = idx >> 9, p = idx & 511;
        float v = PINF;
        if (p < 320) v = fmaf(vals[2*p], s_w0[s], fmaf(vals[2*p+1], s_w1[s], s_b[s]));
        srows[idx] = v;
    }
    __syncthreads();
    int w = tid >> 5, lane = tid & 31;
    if (w < 7) {
        float* a = srows + w*512;
        for (int k = 2; k <= 512; k <<= 1) {
            for (int j = k >> 1; j > 0; j >>= 1) {
                #pragma unroll 1
                for (int i = lane; i < 512; i += 32) {
                    int ixj = i ^ j;
                    if (ixj > i) {
                        float xv = a[i], yv = a[ixj];
                        if ((xv > yv) == ((i & k) == 0)) { a[i] = yv; a[ixj] = xv; }
                    }
                }
                __syncwarp();
            }
        }
    }
    __syncthreads();
    if (tid < 64) {
        int i = tid >> 3, j = tid & 7;
        float s1i = 0.f, s2ij = 0.f;
        float s3[8];
        #pragma unroll
        for (int kk = 0; kk < 8; kk++) s3[kk] = 0.f;
        float cur[7];
        #pragma unroll
        for (int d = 0; d < 7; d++) cur[d] = srows[d*512];
        float dx[8];
        dx[0] = DTT;
        for (int p = 0; p < 319; p++) {
            #pragma unroll
            for (int d = 0; d < 7; d++) {
                float nx = srows[d*512 + p + 1];
                dx[d+1] = nx - cur[d];
                cur[d] = nx;
            }
            float dxi = dx[i], dxj = dx[j];
            float c = fmaf(dxj, fmaf(dxi, (1.f/6.f), 0.5f*s1i), s2ij);
            #pragma unroll
            for (int kk = 0; kk < 8; kk++) s3[kk] = fmaf(c, dx[kk], s3[kk]);
            s2ij = fmaf(dxj, fmaf(0.5f, dxi, s1i), s2ij);
            s1i += dxi;
        }
        int l = row >> 3, fi = row & 7;
        float* out = g_x + l*FINALW + fi*(2*SIGLEN) + which*SIGLEN;
        if (j == 0) out[i] = s1i;
        out[8 + tid] = s2ij;
        #pragma unroll
        for (int kk = 0; kk < 8; kk++) out[72 + tid*8 + kk] = s3[kk];
    }
}

// ----------------------- final dot + BatchNorm over L=32 ------------------------
__global__ void k_final(const float* __restrict__ Wf, const float* __restrict__ gfin,
                        const float* __restrict__ betafin, float* __restrict__ out) {
    int w = threadIdx.x >> 5, lane = threadIdx.x & 31;
    const float* xr = g_x + w*FINALW;
    float p = 0.f;
    for (int i = lane; i < FINALW; i += 32) p = fmaf(xr[i], Wf[i], p);
    #pragma unroll
    for (int o = 16; o > 0; o >>= 1) p += __shfl_down_sync(0xffffffffu, p, o);
    __shared__ double s_out[32];
    if (lane == 0) s_out[w] = p;
    __syncthreads();
    __shared__ double sm[2];
    if (threadIdx.x == 0) {
        double S = 0.0, Q = 0.0;
        for (int i = 0; i < 32; i++) { S += s_out[i]; Q += s_out[i]*s_out[i]; }
        double mean = S/32.0;
        sm[0] = mean; sm[1] = Q/32.0 - mean*mean;
    }
    __syncthreads();
    if (threadIdx.x < 32) {
        double r = (s_out[threadIdx.x] - sm[0]) / sqrt(sm[1] + (double)EPSB);
        out[threadIdx.x] = (float)(r*(double)gfin[0] + (double)betafin[0]);
    }
}

// --------------------------------- launcher -------------------------------------
extern "C" void kernel_launch(void* const* d_in, const int* in_sizes, int n_in,
                              void* d_out, int out_size) {
    const float* eigenvalues = (const float*)d_in[0];
    const float* eigvec      = (const float*)d_in[1];
    const int*   dgm0        = (const int*)d_in[2];
    const int*   dgm1rel     = (const int*)d_in[3];
    const int*   dgm1ext     = (const int*)d_in[4];
    const float* mlp_Win     = (const float*)d_in[5];
    const float* mlp_gin     = (const float*)d_in[7];
    const float* mlp_betain  = (const float*)d_in[8];
    const float* mlp_Wh      = (const float*)d_in[9];
    const float* mlp_gh      = (const float*)d_in[11];
    const float* mlp_betah   = (const float*)d_in[12];
    const float* mlp_Wout    = (const float*)d_in[13];
    const float* mlp_gout    = (const float*)d_in[15];
    const float* mlp_betaout = (const float*)d_in[16];
    const float* W_proj      = (const float*)d_in[17];
    const float* b_proj      = (const float*)d_in[18];
    const float* W_fin       = (const float*)d_in[19];
    const float* g_fin       = (const float*)d_in[21];
    const float* beta_fin    = (const float*)d_in[22];
    float* out = (float*)d_out;

    k_xstats<<<1, 1024>>>(eigenvalues, mlp_Win, mlp_gin, mlp_betain);
    k_build1<<<8, 128>>>(mlp_Wh);
    k_seg<<<dim3(128, 8), 256>>>(eigenvalues);
    k_segstats<<<dim3(16, 8), 256>>>(eigenvalues);
    k_bncoef2<<<8, 128>>>(mlp_gh, mlp_betah);
    k_a2<<<dim3(256, 8), 256>>>(eigenvalues);
    k_gemm<<<dim3(256, 8), 256>>>(mlp_Wh);
    k_bncoef3<<<8, 1024>>>(mlp_gh, mlp_betah);
    k_out<<<dim3(64, 8), 256>>>(mlp_Wout);
    k_bnO<<<1, 32>>>(mlp_gout, mlp_betaout);
    k_einsum<<<dim3(4, 32), 256>>>(eigvec);
    k_sig<<<512, 256>>>(dgm0, dgm1rel, dgm1ext, W_proj, b_proj);
    k_final<<<1, 1024>>>(W_fin, g_fin, beta_fin, out);
}

// round 7
// speedup vs baseline: 1.4227x; 1.4227x over previous
#include <cuda_runtime.h>
#include <math.h>
#include <stdint.h>

#define NSAMP 32768
#define FF 8
#define HU 128
#define VV 2048
#define LL 32
#define EE 1024
#define EPSB 1e-5f
#define DTT (1.0f/51360.0f)
#define SIGLEN 584
#define FINALW 9344
#define NSEG 129

typedef unsigned long long u64;

// ---- packed f32x2 helpers (Blackwell) ----
#define FMA2(d, a, b, c) asm("fma.rn.f32x2 %0, %1, %2, %3;" : "=l"(d) : "l"(a), "l"(b), "l"(c))
#define ADD2(d, a, b)    asm("add.rn.f32x2 %0, %1, %2;" : "=l"(d) : "l"(a), "l"(b))
#define PACKDUPF(out, f) asm("mov.b64 %0, {%1, %1};" : "=l"(out) : "f"(f))
#define UNPACKF(lo, hi, v) asm("mov.b64 {%0, %1}, %2;" : "=f"(lo), "=f"(hi) : "l"(v))

// ------------------------- scratch (__device__ globals) -------------------------
__device__ float g_bufB[(size_t)FF*NSAMP*HU];   // layer-3 preacts
__device__ float g_yout[FF*NSAMP];
__device__ float g_cA[FF*HU], g_cB[FF*HU];
__device__ float g_scl3[FF*HU], g_shf3[FF*HU];
__device__ float g_sclO[FF], g_shfO[FF];
__device__ float g_partF[(size_t)FF*256*2*128];
__device__ double g_partO[FF*64*2];
__device__ float g_fv[(size_t)LL*FF*VV];
__device__ float g_x[LL*FINALW];
// piecewise-linear layer-2 machinery
__device__ float g_T[FF][HU];                   // sorted knots
__device__ float g_P[FF][NSEG][HU], g_Q[FF][NSEG][HU];      // Y2 = P*x+Q per segment
__device__ float g_PP[FF][NSEG][HU], g_QQ[FF][NSEG][HU];    // a2 = relu(PP*x+QQ)
__device__ int   g_seg[FF*NSAMP];
__device__ double g_cumC[FF][HU], g_cumX[FF][HU], g_cumXX[FF][HU]; // cumulative F(s)
__device__ double g_totS, g_totQ;               // global Σx, Σx²

// --------------- x batch stats + analytic layer-1 BN coefficients ---------------
__global__ void k_xstats(const float* __restrict__ x, const float* __restrict__ Win,
                         const float* __restrict__ gin, const float* __restrict__ betain) {
    __shared__ double rs[1024], rq[1024];
    __shared__ double sm[2];
    int t = threadIdx.x;
    double s = 0.0, q = 0.0;
    for (int i = t; i < NSAMP; i += 1024) { double v = x[i]; s += v; q += v*v; }
    rs[t] = s; rq[t] = q; __syncthreads();
    for (int o = 512; o > 0; o >>= 1) {
        if (t < o) { rs[t] += rs[t+o]; rq[t] += rq[t+o]; }
        __syncthreads();
    }
    if (t == 0) {
        double mx = rs[0]/(double)NSAMP;
        sm[0] = mx; sm[1] = rq[0]/(double)NSAMP - mx*mx;
        g_totS = rs[0]; g_totQ = rq[0];
    }
    __syncthreads();
    double mx = sm[0], vx = sm[1];
    double w  = Win[t];
    double g  = gin[t];
    double be = betain[t];
    double cA = w * g / sqrt(w*w*vx + (double)EPSB);
    g_cA[t] = (float)cA;
    g_cB[t] = (float)(be - cA*mx);
}

// ---------------- build sorted knots + per-segment (P,Q) via prefix scan --------
__global__ void __launch_bounds__(128) k_build1(const float* __restrict__ Wh) {
    int f = blockIdx.x, tid = threadIdx.x;
    __shared__ float sT[128], s_cA[128], s_cB[128];
    __shared__ int sK[128];
    __shared__ unsigned char s_init[128];
    float ca = g_cA[f*HU + tid], cb = g_cB[f*HU + tid];
    s_cA[tid] = ca; s_cB[tid] = cb;
    float t;
    if (ca == 0.f) t = __int_as_float(0x7f800000);
    else t = -cb/ca;
    sT[tid] = t; sK[tid] = tid;
    s_init[tid] = (ca < 0.f) || (ca == 0.f && cb > 0.f);
    __syncthreads();
    for (int k = 2; k <= 128; k <<= 1) {
        for (int j = k >> 1; j > 0; j >>= 1) {
            int ixj = tid ^ j;
            if (ixj > tid) {
                float a = sT[tid], b = sT[ixj];
                bool up = ((tid & k) == 0);
                if ((a > b) == up) {
                    sT[tid] = b; sT[ixj] = a;
                    int ka = sK[tid]; sK[tid] = sK[ixj]; sK[ixj] = ka;
                }
            }
            __syncthreads();
        }
    }
    g_T[f][tid] = sT[tid];
    const float* W = Wh + (size_t)f*2*HU*HU;
    float p = 0.f, q = 0.f;
    for (int k = 0; k < 128; k++) {
        if (s_init[k]) {
            float w = W[tid*HU + k];
            p = fmaf(w, s_cA[k], p);
            q = fmaf(w, s_cB[k], q);
        }
    }
    g_P[f][0][tid] = p; g_Q[f][0][tid] = q;
    for (int s = 1; s < NSEG; s++) {
        int ks = sK[s-1];
        float cka = s_cA[ks];
        if (cka != 0.f) {
            float w = W[tid*HU + ks];
            float sgn = (cka > 0.f) ? 1.f : -1.f;
            p = fmaf(sgn*w, cka, p);
            q = fmaf(sgn*w, s_cB[ks], q);
        }
        g_P[f][s][tid] = p; g_Q[f][s][tid] = q;
    }
}

// ---------------------------- segment id per sample -----------------------------
__global__ void __launch_bounds__(256) k_seg(const float* __restrict__ x) {
    int f = blockIdx.y;
    __shared__ float sT[128];
    if (threadIdx.x < 128) sT[threadIdx.x] = g_T[f][threadIdx.x];
    __syncthreads();
    int n = blockIdx.x*256 + threadIdx.x;
    float xv = x[n];
    int lo = 0, hi = 128;
    #pragma unroll
    for (int it = 0; it < 7; it++) {
        int mid = (lo + hi) >> 1;
        if (sT[mid] < xv) lo = mid + 1; else hi = mid;
    }
    if (lo < hi && sT[lo] < xv) lo++;
    g_seg[f*NSAMP + n] = lo;
}

// ------- cumulative F(s) = (cnt, Σx, Σx²) over {x ≤ t_s}; x is L2-resident ------
__global__ void __launch_bounds__(256) k_cumstats(const float* __restrict__ x) {
    int s = blockIdx.x, f = blockIdx.y, tid = threadIdx.x;
    float t = g_T[f][s];
    int   c  = 0;
    float s1a = 0.f, s1b = 0.f, s2a = 0.f, s2b = 0.f;  // dual accumulators
    #pragma unroll 4
    for (int n = tid; n < NSAMP; n += 512) {
        float va = x[n];
        float vb = x[n + 256];
        if (va <= t) { c++; s1a += va; s2a = fmaf(va, va, s2a); }
        if (vb <= t) { c++; s1b += vb; s2b = fmaf(vb, vb, s2b); }
    }
    __shared__ double shC[256], shX[256], shXX[256];
    shC[tid]  = (double)c;
    shX[tid]  = (double)s1a + (double)s1b;
    shXX[tid] = (double)s2a + (double)s2b;
    __syncthreads();
    for (int o = 128; o > 0; o >>= 1) {
        if (tid < o) { shC[tid] += shC[tid+o]; shX[tid] += shX[tid+o]; shXX[tid] += shXX[tid+o]; }
        __syncthreads();
    }
    if (tid == 0) {
        g_cumC[f][s] = shC[0]; g_cumX[f][s] = shX[0]; g_cumXX[f][s] = shXX[0];
    }
}

// --------- layer-2 BN coefs from cumulative aggregates + fused PP/QQ tables -----
__global__ void __launch_bounds__(128) k_bncoef2(const float* __restrict__ gh,
                                                 const float* __restrict__ betah) {
    int f = blockIdx.x, j = threadIdx.x;
    __shared__ double shC[NSEG], shX[NSEG], shXX[NSEG];
    for (int s = j; s < NSEG; s += 128) {
        double c, xs, xx;
        if (s == 0)           { c = g_cumC[f][0];                 xs = g_cumX[f][0];                 xx = g_cumXX[f][0]; }
        else if (s < NSEG-1)  { c = g_cumC[f][s] - g_cumC[f][s-1]; xs = g_cumX[f][s] - g_cumX[f][s-1]; xx = g_cumXX[f][s] - g_cumXX[f][s-1]; }
        else                  { c = (double)NSAMP - g_cumC[f][127]; xs = g_totS - g_cumX[f][127];     xx = g_totQ - g_cumXX[f][127]; }
        shC[s] = c; shX[s] = xs; shXX[s] = xx;
    }
    __syncthreads();
    double S = 0.0, Q2 = 0.0;
    for (int s = 0; s < NSEG; s++) {
        double p = g_P[f][s][j], q = g_Q[f][s][j];
        S  += p*shX[s] + q*shC[s];
        Q2 += p*p*shXX[s] + 2.0*p*q*shX[s] + q*q*shC[s];
    }
    double mean = S/(double)NSAMP;
    double var  = Q2/(double)NSAMP - mean*mean;
    double g  = gh[f*2*HU + j];
    double be = betah[f*2*HU + j];
    double scl = g / sqrt(var + (double)EPSB);
    double shf = be - scl*mean;
    for (int s = 0; s < NSEG; s++) {
        float p = g_P[f][s][j], q = g_Q[f][s][j];
        g_PP[f][s][j] = (float)(scl*(double)p);
        g_QQ[f][s][j] = (float)(scl*(double)q + shf);
    }
}

// ---------------- hidden-layer GEMM (f32x2), A generated in-place ---------------
// A[n][k] = relu(PP[f][seg[n]][k]*x[n] + QQ[f][seg[n]][k]); Y -> g_bufB
__global__ void __launch_bounds__(256, 2) k_gemm(const float* __restrict__ x,
                                                 const float* __restrict__ Wh) {
    __shared__ __align__(16) float As[32][132];
    __shared__ __align__(16) float Bs[32][132];
    __shared__ float sx[128];
    __shared__ int ssg[128];

    int f = blockIdx.y, bx = blockIdx.x, m0 = bx * 128, tid = threadIdx.x;
    int tx = tid & 15, ty = tid >> 4;

    if (tid < 128) {
        sx[tid]  = x[m0 + tid];
        ssg[tid] = g_seg[f*NSAMP + m0 + tid];
    }
    __syncthreads();

    const float* W = Wh + ((size_t)f*2 + 1)*HU*HU;
    const float* PPf = &g_PP[f][0][0];
    const float* QQf = &g_QQ[f][0][0];

    u64 acc[8][4];
    #pragma unroll
    for (int r = 0; r < 8; r++)
        #pragma unroll
        for (int c = 0; c < 4; c++) acc[r][c] = 0ull;

    for (int k0 = 0; k0 < HU; k0 += 32) {
        #pragma unroll
        for (int i = 0; i < 16; i++) {
            int idx = tid + i*256;
            int kk = idx & 31, n = idx >> 5;
            int sgn = ssg[n];
            float a = fmaf(PPf[sgn*HU + k0 + kk], sx[n], QQf[sgn*HU + k0 + kk]);
            As[kk][n] = fmaxf(a, 0.f);
            Bs[kk][n] = W[n*HU + k0 + kk];
        }
        __syncthreads();
        #pragma unroll
        for (int kk = 0; kk < 32; kk++) {
            float a[8];
            *(float4*)(a)   = *(const float4*)&As[kk][ty*8];
            *(float4*)(a+4) = *(const float4*)&As[kk][ty*8+4];
            u64 b[4];
            *(ulonglong2*)(b)   = *(const ulonglong2*)&Bs[kk][tx*8];
            *(ulonglong2*)(b+2) = *(const ulonglong2*)&Bs[kk][tx*8+4];
            #pragma unroll
            for (int r = 0; r < 8; r++) {
                u64 a2;
                PACKDUPF(a2, a[r]);
                #pragma unroll
                for (int c = 0; c < 4; c++) FMA2(acc[r][c], a2, b[c], acc[r][c]);
            }
        }
        __syncthreads();
    }

    #pragma unroll
    for (int r = 0; r < 8; r++) {
        size_t base = ((size_t)f*NSAMP + m0 + ty*8 + r)*HU + tx*8;
        ulonglong2 v0; v0.x = acc[r][0]; v0.y = acc[r][1];
        ulonglong2 v1; v1.x = acc[r][2]; v1.y = acc[r][3];
        *(ulonglong2*)&g_bufB[base]   = v0;
        *(ulonglong2*)&g_bufB[base+4] = v1;
    }

    u64 s2[4], q2[4];
    #pragma unroll
    for (int c = 0; c < 4; c++) { s2[c] = 0ull; q2[c] = 0ull; }
    #pragma unroll
    for (int r = 0; r < 8; r++)
        #pragma unroll
        for (int c = 0; c < 4; c++) {
            ADD2(s2[c], s2[c], acc[r][c]);
            FMA2(q2[c], acc[r][c], acc[r][c], q2[c]);
        }
    __syncthreads();
    u64* sh = (u64*)&As[0][0];
    #pragma unroll
    for (int c = 0; c < 4; c++) {
        sh[(ty*16 + tx)*4 + c]        = s2[c];
        sh[1024 + (ty*16 + tx)*4 + c] = q2[c];
    }
    __syncthreads();
    if (tid < 64) {
        int txx = tid >> 2, cpi = tid & 3;
        u64 S = 0ull, Q = 0ull;
        #pragma unroll
        for (int t2 = 0; t2 < 16; t2++) {
            ADD2(S, S, sh[(t2*16 + txx)*4 + cpi]);
            ADD2(Q, Q, sh[1024 + (t2*16 + txx)*4 + cpi]);
        }
        float slo, shi, qlo, qhi;
        UNPACKF(slo, shi, S);
        UNPACKF(qlo, qhi, Q);
        int col = txx*8 + cpi*2;
        float* P = g_partF + (((size_t)f*256 + bx)*2)*128;
        P[col] = slo; P[col+1] = shi;
        P[128+col] = qlo; P[128+col+1] = qhi;
    }
}

// --------------------- BN coefficients from GEMM partials -----------------------
__global__ void k_bncoef3(const float* __restrict__ gh, const float* __restrict__ betah) {
    int f = blockIdx.x;
    int u = threadIdx.x & 127, h = threadIdx.x >> 7;
    double S = 0.0, Q = 0.0;
    #pragma unroll 8
    for (int b = h; b < 256; b += 8) {
        const float* P = g_partF + (((size_t)f*256 + b)*2)*128;
        S += P[u]; Q += P[128+u];
    }
    __shared__ double shS[1024], shQ[1024];
    shS[h*128+u] = S; shQ[h*128+u] = Q;
    __syncthreads();
    if (h == 0) {
        #pragma unroll
        for (int i = 1; i < 8; i++) { S += shS[i*128+u]; Q += shQ[i*128+u]; }
        double mean = S/(double)NSAMP;
        double var  = Q/(double)NSAMP - mean*mean;
        double g  = gh[f*2*HU + HU + u];
        double be = betah[f*2*HU + HU + u];
        double scl = g / sqrt(var + (double)EPSB);
        g_scl3[f*HU+u] = (float)scl;
        g_shf3[f*HU+u] = (float)(be - scl*mean);
    }
}

// ---------------------- output layer: dot + stats -------------------------------
__global__ void __launch_bounds__(256) k_out(const float* __restrict__ Wout) {
    int f = blockIdx.y;
    int w = threadIdx.x >> 5, lane = threadIdx.x & 31;
    __shared__ float s_w[HU], s_scl[HU], s_shf[HU];
    if (threadIdx.x < 128) {
        s_w[threadIdx.x]   = Wout[f*HU + threadIdx.x];
        s_scl[threadIdx.x] = g_scl3[f*HU + threadIdx.x];
        s_shf[threadIdx.x] = g_shf3[f*HU + threadIdx.x];
    }
    __syncthreads();
    int wg = blockIdx.x*8 + w;
    int n0 = wg*64;
    float w0 = s_w[lane*4], w1 = s_w[lane*4+1], w2 = s_w[lane*4+2], w3 = s_w[lane*4+3];
    float c0 = s_scl[lane*4], c1 = s_scl[lane*4+1], c2 = s_scl[lane*4+2], c3 = s_scl[lane*4+3];
    float h0 = s_shf[lane*4], h1 = s_shf[lane*4+1], h2 = s_shf[lane*4+2], h3 = s_shf[lane*4+3];
    double s = 0.0, q = 0.0;
    for (int n = n0; n < n0 + 64; n++) {
        float4 y = *(const float4*)&g_bufB[((size_t)f*NSAMP + n)*HU + lane*4];
        float p = fmaxf(fmaf(y.x, c0, h0), 0.f)*w0 + fmaxf(fmaf(y.y, c1, h1), 0.f)*w1
                + fmaxf(fmaf(y.z, c2, h2), 0.f)*w2 + fmaxf(fmaf(y.w, c3, h3), 0.f)*w3;
        #pragma unroll
        for (int o = 16; o > 0; o >>= 1) p += __shfl_down_sync(0xffffffffu, p, o);
        if (lane == 0) { g_yout[f*NSAMP + n] = p; s += p; q += (double)p*p; }
    }
    __shared__ double sh_s[8], sh_q[8];
    if (lane == 0) { sh_s[w] = s; sh_q[w] = q; }
    __syncthreads();
    if (threadIdx.x == 0) {
        double S = 0.0, Q = 0.0;
        for (int i = 0; i < 8; i++) { S += sh_s[i]; Q += sh_q[i]; }
        g_partO[(f*64 + blockIdx.x)*2 + 0] = S;
        g_partO[(f*64 + blockIdx.x)*2 + 1] = Q;
    }
}

__global__ void k_bnO(const float* __restrict__ gout, const float* __restrict__ betaout) {
    int f = threadIdx.x;
    if (f >= FF) return;
    double S = 0.0, Q = 0.0;
    for (int b = 0; b < 64; b++) { S += g_partO[(f*64+b)*2]; Q += g_partO[(f*64+b)*2+1]; }
    double mean = S/(double)NSAMP;
    double var  = Q/(double)NSAMP - mean*mean;
    double scl = (double)gout[f] / sqrt(var + (double)EPSB);
    g_sclO[f] = (float)scl;
    g_shfO[f] = (float)((double)betaout[f] - scl*mean);
}

// ---------------------- einsum: fv[l][f][v] = sum_e evs * eigvec ----------------
__global__ void __launch_bounds__(256) k_einsum(const float* __restrict__ eigvec) {
    int l = blockIdx.y;
    int v0 = blockIdx.x*512 + threadIdx.x*2;
    __shared__ float evs[FF][EE];
    for (int idx = threadIdx.x; idx < FF*EE; idx += 256) {
        int f = idx >> 10, e = idx & 1023;
        float y = g_yout[f*NSAMP + l*EE + e];
        evs[f][e] = fmaxf(fmaf(y, g_sclO[f], g_shfO[f]), 0.f);
    }
    __syncthreads();
    float2 acc[FF];
    #pragma unroll
    for (int f = 0; f < FF; f++) acc[f] = make_float2(0.f, 0.f);
    const float* base = eigvec + ((size_t)l*EE)*VV + v0;
    #pragma unroll 4
    for (int e = 0; e < EE; e++) {
        float2 wv = *(const float2*)(base + (size_t)e*VV);
        #pragma unroll
        for (int f = 0; f < FF; f++) {
            float ev = evs[f][e];
            acc[f].x = fmaf(ev, wv.x, acc[f].x);
            acc[f].y = fmaf(ev, wv.y, acc[f].y);
        }
    }
    #pragma unroll
    for (int f = 0; f < FF; f++)
        *(float2*)&g_fv[((size_t)l*FF + f)*VV + v0] = acc[f];
}

// -------------------- gather + project + sort + level-3 signature ---------------
__global__ void __launch_bounds__(256) k_sig(const int* __restrict__ dgm0,
                                             const int* __restrict__ dgm1rel,
                                             const int* __restrict__ dgm1ext,
                                             const float* __restrict__ Wp,
                                             const float* __restrict__ bp) {
    int bid = blockIdx.x;
    int which = bid & 1;
    int row = bid >> 1;
    int tid = threadIdx.x;
    __shared__ float vals[640];
    __shared__ float srows[7*512];
    __shared__ float s_w0[7], s_w1[7], s_b[7];
    const float* fvr = g_fv + (size_t)row*VV;
    if (tid < 7) { s_w0[tid] = Wp[tid*2]; s_w1[tid] = Wp[tid*2+1]; s_b[tid] = bp[tid]; }
    for (int t = tid; t < 640; t += 256) {
        int src;
        if (which)        src = dgm1ext[row*640 + t];
        else if (t < 512) src = dgm0[row*512 + t];
        else              src = dgm1rel[row*129 + (128 - (t - 512))];
        vals[t] = fvr[src];
    }
    __syncthreads();
    const float PINF = __int_as_float(0x7f800000);
    for (int idx = tid; idx < 7*512; idx += 256) {
        int s = idx >> 9, p = idx & 511;
        float v = PINF;
        if (p < 320) v = fmaf(vals[2*p], s_w0[s], fmaf(vals[2*p+1], s_w1[s], s_b[s]));
        srows[idx] = v;
    }
    __syncthreads();
    int w = tid >> 5, lane = tid & 31;
    if (w < 7) {
        float* a = srows + w*512;
        for (int k = 2; k <= 512; k <<= 1) {
            for (int j = k >> 1; j > 0; j >>= 1) {
                #pragma unroll 1
                for (int i = lane; i < 512; i += 32) {
                    int ixj = i ^ j;
                    if (ixj > i) {
                        float xv = a[i], yv = a[ixj];
                        if ((xv > yv) == ((i & k) == 0)) { a[i] = yv; a[ixj] = xv; }
                    }
                }
                __syncwarp();
            }
        }
    }
    __syncthreads();
    if (tid < 64) {
        int i = tid >> 3, j = tid & 7;
        float s1i = 0.f, s2ij = 0.f;
        float s3[8];
        #pragma unroll
        for (int kk = 0; kk < 8; kk++) s3[kk] = 0.f;
        float cur[7];
        #pragma unroll
        for (int d = 0; d < 7; d++) cur[d] = srows[d*512];
        float dx[8];
        dx[0] = DTT;
        for (int p = 0; p < 319; p++) {
            #pragma unroll
            for (int d = 0; d < 7; d++) {
                float nx = srows[d*512 + p + 1];
                dx[d+1] = nx - cur[d];
                cur[d] = nx;
            }
            float dxi = dx[i], dxj = dx[j];
            float c = fmaf(dxj, fmaf(dxi, (1.f/6.f), 0.5f*s1i), s2ij);
            #pragma unroll
            for (int kk = 0; kk < 8; kk++) s3[kk] = fmaf(c, dx[kk], s3[kk]);
            s2ij = fmaf(dxj, fmaf(0.5f, dxi, s1i), s2ij);
            s1i += dxi;
        }
        int l = row >> 3, fi = row & 7;
        float* out = g_x + l*FINALW + fi*(2*SIGLEN) + which*SIGLEN;
        if (j == 0) out[i] = s1i;
        out[8 + tid] = s2ij;
        #pragma unroll
        for (int kk = 0; kk < 8; kk++) out[72 + tid*8 + kk] = s3[kk];
    }
}

// ----------------------- final dot + BatchNorm over L=32 ------------------------
__global__ void k_final(const float* __restrict__ Wf, const float* __restrict__ gfin,
                        const float* __restrict__ betafin, float* __restrict__ out) {
    int w = threadIdx.x >> 5, lane = threadIdx.x & 31;
    const float* xr = g_x + w*FINALW;
    float p = 0.f;
    for (int i = lane; i < FINALW; i += 32) p = fmaf(xr[i], Wf[i], p);
    #pragma unroll
    for (int o = 16; o > 0; o >>= 1) p += __shfl_down_sync(0xffffffffu, p, o);
    __shared__ double s_out[32];
    if (lane == 0) s_out[w] = p;
    __syncthreads();
    __shared__ double sm[2];
    if (threadIdx.x == 0) {
        double S = 0.0, Q = 0.0;
        for (int i = 0; i < 32; i++) { S += s_out[i]; Q += s_out[i]*s_out[i]; }
        double mean = S/32.0;
        sm[0] = mean; sm[1] = Q/32.0 - mean*mean;
    }
    __syncthreads();
    if (threadIdx.x < 32) {
        double r = (s_out[threadIdx.x] - sm[0]) / sqrt(sm[1] + (double)EPSB);
        out[threadIdx.x] = (float)(r*(double)gfin[0] + (double)betafin[0]);
    }
}

// --------------------------------- launcher -------------------------------------
extern "C" void kernel_launch(void* const* d_in, const int* in_sizes, int n_in,
                              void* d_out, int out_size) {
    const float* eigenvalues = (const float*)d_in[0];
    const float* eigvec      = (const float*)d_in[1];
    const int*   dgm0        = (const int*)d_in[2];
    const int*   dgm1rel     = (const int*)d_in[3];
    const int*   dgm1ext     = (const int*)d_in[4];
    const float* mlp_Win     = (const float*)d_in[5];
    const float* mlp_gin     = (const float*)d_in[7];
    const float* mlp_betain  = (const float*)d_in[8];
    const float* mlp_Wh      = (const float*)d_in[9];
    const float* mlp_gh      = (const float*)d_in[11];
    const float* mlp_betah   = (const float*)d_in[12];
    const float* mlp_Wout    = (const float*)d_in[13];
    const float* mlp_gout    = (const float*)d_in[15];
    const float* mlp_betaout = (const float*)d_in[16];
    const float* W_proj      = (const float*)d_in[17];
    const float* b_proj      = (const float*)d_in[18];
    const float* W_fin       = (const float*)d_in[19];
    const float* g_fin       = (const float*)d_in[21];
    const float* beta_fin    = (const float*)d_in[22];
    float* out = (float*)d_out;

    k_xstats<<<1, 1024>>>(eigenvalues, mlp_Win, mlp_gin, mlp_betain);
    k_build1<<<8, 128>>>(mlp_Wh);
    k_seg<<<dim3(128, 8), 256>>>(eigenvalues);
    k_cumstats<<<dim3(128, 8), 256>>>(eigenvalues);
    k_bncoef2<<<8, 128>>>(mlp_gh, mlp_betah);
    k_gemm<<<dim3(256, 8), 256>>>(eigenvalues, mlp_Wh);
    k_bncoef3<<<8, 1024>>>(mlp_gh, mlp_betah);
    k_out<<<dim3(64, 8), 256>>>(mlp_Wout);
    k_bnO<<<1, 32>>>(mlp_gout, mlp_betaout);
    k_einsum<<<dim3(4, 32), 256>>>(eigvec);
    k_sig<<<512, 256>>>(dgm0, dgm1rel, dgm1ext, W_proj, b_proj);
    k_final<<<1, 1024>>>(W_fin, g_fin, beta_fin, out);
}

// round 8
// speedup vs baseline: 1.5148x; 1.0647x over previous
#include <cuda_runtime.h>
#include <math.h>
#include <stdint.h>

#define NSAMP 32768
#define FF 8
#define HU 128
#define VV 2048
#define LL 32
#define EE 1024
#define EPSB 1e-5f
#define DTT (1.0f/51360.0f)
#define SIGLEN 584
#define FINALW 9344
#define NSEG 129

typedef unsigned long long u64;

// ---- packed f32x2 helpers (Blackwell) ----
#define FMA2(d, a, b, c) asm("fma.rn.f32x2 %0, %1, %2, %3;" : "=l"(d) : "l"(a), "l"(b), "l"(c))
#define ADD2(d, a, b)    asm("add.rn.f32x2 %0, %1, %2;" : "=l"(d) : "l"(a), "l"(b))
#define PACKDUPF(out, f) asm("mov.b64 %0, {%1, %1};" : "=l"(out) : "f"(f))
#define UNPACKF(lo, hi, v) asm("mov.b64 {%0, %1}, %2;" : "=f"(lo), "=f"(hi) : "l"(v))

// ------------------------- scratch (__device__ globals) -------------------------
__device__ float g_bufB[(size_t)FF*NSAMP*HU];   // layer-3 preacts
__device__ float g_yout[FF*NSAMP];
__device__ float g_cA[FF*HU], g_cB[FF*HU];
__device__ float g_scl3[FF*HU], g_shf3[FF*HU];
__device__ float g_sclO[FF], g_shfO[FF];
__device__ float g_partF[(size_t)FF*256*2*128];
__device__ double g_partO[FF*64*2];
__device__ float g_fv[(size_t)LL*FF*VV];
__device__ float g_x[LL*FINALW];
// piecewise-linear layer-2 machinery
__device__ float g_T[FF][HU];                   // sorted knots
__device__ float g_P[FF][NSEG][HU], g_Q[FF][NSEG][HU];      // Y2 = P*x+Q per segment
__device__ float g_PP[FF][NSEG][HU], g_QQ[FF][NSEG][HU];    // a2 = relu(PP*x+QQ)
__device__ int   g_seg[FF*NSAMP];
__device__ double g_cumC[FF][HU], g_cumX[FF][HU], g_cumXX[FF][HU]; // cumulative F(s)
__device__ double g_totS, g_totQ;               // global Σx, Σx²

// --------------- x batch stats + analytic layer-1 BN coefficients ---------------
__global__ void k_xstats(const float* __restrict__ x, const float* __restrict__ Win,
                         const float* __restrict__ gin, const float* __restrict__ betain) {
    __shared__ double rs[1024], rq[1024];
    __shared__ double sm[2];
    int t = threadIdx.x;
    double s = 0.0, q = 0.0;
    for (int i = t; i < NSAMP; i += 1024) { double v = x[i]; s += v; q += v*v; }
    rs[t] = s; rq[t] = q; __syncthreads();
    for (int o = 512; o > 0; o >>= 1) {
        if (t < o) { rs[t] += rs[t+o]; rq[t] += rq[t+o]; }
        __syncthreads();
    }
    if (t == 0) {
        double mx = rs[0]/(double)NSAMP;
        sm[0] = mx; sm[1] = rq[0]/(double)NSAMP - mx*mx;
        g_totS = rs[0]; g_totQ = rq[0];
    }
    __syncthreads();
    double mx = sm[0], vx = sm[1];
    double w  = Win[t];
    double g  = gin[t];
    double be = betain[t];
    double cA = w * g / sqrt(w*w*vx + (double)EPSB);
    g_cA[t] = (float)cA;
    g_cB[t] = (float)(be - cA*mx);
}

// ---------------- build sorted knots + per-segment (P,Q) via prefix scan --------
__global__ void __launch_bounds__(128) k_build1(const float* __restrict__ Wh) {
    int f = blockIdx.x, tid = threadIdx.x;
    __shared__ float sT[128], s_cA[128], s_cB[128];
    __shared__ int sK[128];
    __shared__ unsigned char s_init[128];
    float ca = g_cA[f*HU + tid], cb = g_cB[f*HU + tid];
    s_cA[tid] = ca; s_cB[tid] = cb;
    float t;
    if (ca == 0.f) t = __int_as_float(0x7f800000);
    else t = -cb/ca;
    sT[tid] = t; sK[tid] = tid;
    s_init[tid] = (ca < 0.f) || (ca == 0.f && cb > 0.f);
    __syncthreads();
    for (int k = 2; k <= 128; k <<= 1) {
        for (int j = k >> 1; j > 0; j >>= 1) {
            int ixj = tid ^ j;
            if (ixj > tid) {
                float a = sT[tid], b = sT[ixj];
                bool up = ((tid & k) == 0);
                if ((a > b) == up) {
                    sT[tid] = b; sT[ixj] = a;
                    int ka = sK[tid]; sK[tid] = sK[ixj]; sK[ixj] = ka;
                }
            }
            __syncthreads();
        }
    }
    g_T[f][tid] = sT[tid];
    const float* W = Wh + (size_t)f*2*HU*HU;
    float p = 0.f, q = 0.f;
    for (int k = 0; k < 128; k++) {
        if (s_init[k]) {
            float w = W[tid*HU + k];
            p = fmaf(w, s_cA[k], p);
            q = fmaf(w, s_cB[k], q);
        }
    }
    g_P[f][0][tid] = p; g_Q[f][0][tid] = q;
    for (int s = 1; s < NSEG; s++) {
        int ks = sK[s-1];
        float cka = s_cA[ks];
        if (cka != 0.f) {
            float w = W[tid*HU + ks];
            float sgn = (cka > 0.f) ? 1.f : -1.f;
            p = fmaf(sgn*w, cka, p);
            q = fmaf(sgn*w, s_cB[ks], q);
        }
        g_P[f][s][tid] = p; g_Q[f][s][tid] = q;
    }
}

// ---------------------------- segment id per sample -----------------------------
__global__ void __launch_bounds__(256) k_seg(const float* __restrict__ x) {
    int f = blockIdx.y;
    __shared__ float sT[128];
    if (threadIdx.x < 128) sT[threadIdx.x] = g_T[f][threadIdx.x];
    __syncthreads();
    int n = blockIdx.x*256 + threadIdx.x;
    float xv = x[n];
    int lo = 0, hi = 128;
    #pragma unroll
    for (int it = 0; it < 7; it++) {
        int mid = (lo + hi) >> 1;
        if (sT[mid] < xv) lo = mid + 1; else hi = mid;
    }
    if (lo < hi && sT[lo] < xv) lo++;
    g_seg[f*NSAMP + n] = lo;
}

// ------- cumulative F(s) = (cnt, Σx, Σx²) over {x ≤ t_s}; x is L2-resident ------
__global__ void __launch_bounds__(256) k_cumstats(const float* __restrict__ x) {
    int s = blockIdx.x, f = blockIdx.y, tid = threadIdx.x;
    float t = g_T[f][s];
    int   c  = 0;
    float s1a = 0.f, s1b = 0.f, s2a = 0.f, s2b = 0.f;
    #pragma unroll 4
    for (int n = tid; n < NSAMP; n += 512) {
        float va = x[n];
        float vb = x[n + 256];
        if (va <= t) { c++; s1a += va; s2a = fmaf(va, va, s2a); }
        if (vb <= t) { c++; s1b += vb; s2b = fmaf(vb, vb, s2b); }
    }
    __shared__ double shC[256], shX[256], shXX[256];
    shC[tid]  = (double)c;
    shX[tid]  = (double)s1a + (double)s1b;
    shXX[tid] = (double)s2a + (double)s2b;
    __syncthreads();
    for (int o = 128; o > 0; o >>= 1) {
        if (tid < o) { shC[tid] += shC[tid+o]; shX[tid] += shX[tid+o]; shXX[tid] += shXX[tid+o]; }
        __syncthreads();
    }
    if (tid == 0) {
        g_cumC[f][s] = shC[0]; g_cumX[f][s] = shX[0]; g_cumXX[f][s] = shXX[0];
    }
}

// --------- layer-2 BN coefs from cumulative aggregates + fused PP/QQ tables -----
__global__ void __launch_bounds__(128) k_bncoef2(const float* __restrict__ gh,
                                                 const float* __restrict__ betah) {
    int f = blockIdx.x, j = threadIdx.x;
    __shared__ double shC[NSEG], shX[NSEG], shXX[NSEG];
    for (int s = j; s < NSEG; s += 128) {
        double c, xs, xx;
        if (s == 0)           { c = g_cumC[f][0];                 xs = g_cumX[f][0];                 xx = g_cumXX[f][0]; }
        else if (s < NSEG-1)  { c = g_cumC[f][s] - g_cumC[f][s-1]; xs = g_cumX[f][s] - g_cumX[f][s-1]; xx = g_cumXX[f][s] - g_cumXX[f][s-1]; }
        else                  { c = (double)NSAMP - g_cumC[f][127]; xs = g_totS - g_cumX[f][127];     xx = g_totQ - g_cumXX[f][127]; }
        shC[s] = c; shX[s] = xs; shXX[s] = xx;
    }
    __syncthreads();
    double S = 0.0, Q2 = 0.0;
    for (int s = 0; s < NSEG; s++) {
        double p = g_P[f][s][j], q = g_Q[f][s][j];
        S  += p*shX[s] + q*shC[s];
        Q2 += p*p*shXX[s] + 2.0*p*q*shX[s] + q*q*shC[s];
    }
    double mean = S/(double)NSAMP;
    double var  = Q2/(double)NSAMP - mean*mean;
    double g  = gh[f*2*HU + j];
    double be = betah[f*2*HU + j];
    double scl = g / sqrt(var + (double)EPSB);
    double shf = be - scl*mean;
    for (int s = 0; s < NSEG; s++) {
        float p = g_P[f][s][j], q = g_Q[f][s][j];
        g_PP[f][s][j] = (float)(scl*(double)p);
        g_QQ[f][s][j] = (float)(scl*(double)q + shf);
    }
}

// ---------------- hidden-layer GEMM (f32x2), A generated in-place ---------------
__global__ void __launch_bounds__(256, 2) k_gemm(const float* __restrict__ x,
                                                 const float* __restrict__ Wh) {
    __shared__ __align__(16) float As[32][132];
    __shared__ __align__(16) float Bs[32][132];
    __shared__ float sx[128];
    __shared__ int ssg[128];

    int f = blockIdx.y, bx = blockIdx.x, m0 = bx * 128, tid = threadIdx.x;
    int tx = tid & 15, ty = tid >> 4;

    if (tid < 128) {
        sx[tid]  = x[m0 + tid];
        ssg[tid] = g_seg[f*NSAMP + m0 + tid];
    }
    __syncthreads();

    const float* W = Wh + ((size_t)f*2 + 1)*HU*HU;
    const float* PPf = &g_PP[f][0][0];
    const float* QQf = &g_QQ[f][0][0];

    u64 acc[8][4];
    #pragma unroll
    for (int r = 0; r < 8; r++)
        #pragma unroll
        for (int c = 0; c < 4; c++) acc[r][c] = 0ull;

    for (int k0 = 0; k0 < HU; k0 += 32) {
        #pragma unroll
        for (int i = 0; i < 16; i++) {
            int idx = tid + i*256;
            int kk = idx & 31, n = idx >> 5;
            int sgn = ssg[n];
            float a = fmaf(PPf[sgn*HU + k0 + kk], sx[n], QQf[sgn*HU + k0 + kk]);
            As[kk][n] = fmaxf(a, 0.f);
            Bs[kk][n] = W[n*HU + k0 + kk];
        }
        __syncthreads();
        #pragma unroll
        for (int kk = 0; kk < 32; kk++) {
            float a[8];
            *(float4*)(a)   = *(const float4*)&As[kk][ty*8];
            *(float4*)(a+4) = *(const float4*)&As[kk][ty*8+4];
            u64 b[4];
            *(ulonglong2*)(b)   = *(const ulonglong2*)&Bs[kk][tx*8];
            *(ulonglong2*)(b+2) = *(const ulonglong2*)&Bs[kk][tx*8+4];
            #pragma unroll
            for (int r = 0; r < 8; r++) {
                u64 a2;
                PACKDUPF(a2, a[r]);
                #pragma unroll
                for (int c = 0; c < 4; c++) FMA2(acc[r][c], a2, b[c], acc[r][c]);
            }
        }
        __syncthreads();
    }

    #pragma unroll
    for (int r = 0; r < 8; r++) {
        size_t base = ((size_t)f*NSAMP + m0 + ty*8 + r)*HU + tx*8;
        ulonglong2 v0; v0.x = acc[r][0]; v0.y = acc[r][1];
        ulonglong2 v1; v1.x = acc[r][2]; v1.y = acc[r][3];
        *(ulonglong2*)&g_bufB[base]   = v0;
        *(ulonglong2*)&g_bufB[base+4] = v1;
    }

    u64 s2[4], q2[4];
    #pragma unroll
    for (int c = 0; c < 4; c++) { s2[c] = 0ull; q2[c] = 0ull; }
    #pragma unroll
    for (int r = 0; r < 8; r++)
        #pragma unroll
        for (int c = 0; c < 4; c++) {
            ADD2(s2[c], s2[c], acc[r][c]);
            FMA2(q2[c], acc[r][c], acc[r][c], q2[c]);
        }
    __syncthreads();
    u64* sh = (u64*)&As[0][0];
    #pragma unroll
    for (int c = 0; c < 4; c++) {
        sh[(ty*16 + tx)*4 + c]        = s2[c];
        sh[1024 + (ty*16 + tx)*4 + c] = q2[c];
    }
    __syncthreads();
    if (tid < 64) {
        int txx = tid >> 2, cpi = tid & 3;
        u64 S = 0ull, Q = 0ull;
        #pragma unroll
        for (int t2 = 0; t2 < 16; t2++) {
            ADD2(S, S, sh[(t2*16 + txx)*4 + cpi]);
            ADD2(Q, Q, sh[1024 + (t2*16 + txx)*4 + cpi]);
        }
        float slo, shi, qlo, qhi;
        UNPACKF(slo, shi, S);
        UNPACKF(qlo, qhi, Q);
        int col = txx*8 + cpi*2;
        float* P = g_partF + (((size_t)f*256 + bx)*2)*128;
        P[col] = slo; P[col+1] = shi;
        P[128+col] = qlo; P[128+col+1] = qhi;
    }
}

// --------------------- BN coefficients from GEMM partials -----------------------
__global__ void k_bncoef3(const float* __restrict__ gh, const float* __restrict__ betah) {
    int f = blockIdx.x;
    int u = threadIdx.x & 127, h = threadIdx.x >> 7;
    double S = 0.0, Q = 0.0;
    #pragma unroll 8
    for (int b = h; b < 256; b += 8) {
        const float* P = g_partF + (((size_t)f*256 + b)*2)*128;
        S += P[u]; Q += P[128+u];
    }
    __shared__ double shS[1024], shQ[1024];
    shS[h*128+u] = S; shQ[h*128+u] = Q;
    __syncthreads();
    if (h == 0) {
        #pragma unroll
        for (int i = 1; i < 8; i++) { S += shS[i*128+u]; Q += shQ[i*128+u]; }
        double mean = S/(double)NSAMP;
        double var  = Q/(double)NSAMP - mean*mean;
        double g  = gh[f*2*HU + HU + u];
        double be = betah[f*2*HU + HU + u];
        double scl = g / sqrt(var + (double)EPSB);
        g_scl3[f*HU+u] = (float)scl;
        g_shf3[f*HU+u] = (float)(be - scl*mean);
    }
}

// ---------------------- output layer: dot + stats -------------------------------
__global__ void __launch_bounds__(256) k_out(const float* __restrict__ Wout) {
    int f = blockIdx.y;
    int w = threadIdx.x >> 5, lane = threadIdx.x & 31;
    __shared__ float s_w[HU], s_scl[HU], s_shf[HU];
    if (threadIdx.x < 128) {
        s_w[threadIdx.x]   = Wout[f*HU + threadIdx.x];
        s_scl[threadIdx.x] = g_scl3[f*HU + threadIdx.x];
        s_shf[threadIdx.x] = g_shf3[f*HU + threadIdx.x];
    }
    __syncthreads();
    int wg = blockIdx.x*8 + w;
    int n0 = wg*64;
    float w0 = s_w[lane*4], w1 = s_w[lane*4+1], w2 = s_w[lane*4+2], w3 = s_w[lane*4+3];
    float c0 = s_scl[lane*4], c1 = s_scl[lane*4+1], c2 = s_scl[lane*4+2], c3 = s_scl[lane*4+3];
    float h0 = s_shf[lane*4], h1 = s_shf[lane*4+1], h2 = s_shf[lane*4+2], h3 = s_shf[lane*4+3];
    double s = 0.0, q = 0.0;
    for (int n = n0; n < n0 + 64; n++) {
        float4 y = *(const float4*)&g_bufB[((size_t)f*NSAMP + n)*HU + lane*4];
        float p = fmaxf(fmaf(y.x, c0, h0), 0.f)*w0 + fmaxf(fmaf(y.y, c1, h1), 0.f)*w1
                + fmaxf(fmaf(y.z, c2, h2), 0.f)*w2 + fmaxf(fmaf(y.w, c3, h3), 0.f)*w3;
        #pragma unroll
        for (int o = 16; o > 0; o >>= 1) p += __shfl_down_sync(0xffffffffu, p, o);
        if (lane == 0) { g_yout[f*NSAMP + n] = p; s += p; q += (double)p*p; }
    }
    __shared__ double sh_s[8], sh_q[8];
    if (lane == 0) { sh_s[w] = s; sh_q[w] = q; }
    __syncthreads();
    if (threadIdx.x == 0) {
        double S = 0.0, Q = 0.0;
        for (int i = 0; i < 8; i++) { S += sh_s[i]; Q += sh_q[i]; }
        g_partO[(f*64 + blockIdx.x)*2 + 0] = S;
        g_partO[(f*64 + blockIdx.x)*2 + 1] = Q;
    }
}

__global__ void k_bnO(const float* __restrict__ gout, const float* __restrict__ betaout) {
    int f = threadIdx.x;
    if (f >= FF) return;
    double S = 0.0, Q = 0.0;
    for (int b = 0; b < 64; b++) { S += g_partO[(f*64+b)*2]; Q += g_partO[(f*64+b)*2+1]; }
    double mean = S/(double)NSAMP;
    double var  = Q/(double)NSAMP - mean*mean;
    double scl = (double)gout[f] / sqrt(var + (double)EPSB);
    g_sclO[f] = (float)scl;
    g_shfO[f] = (float)((double)betaout[f] - scl*mean);
}

// ---------------------- einsum: fv[l][f][v] = sum_e evs * eigvec ----------------
__global__ void __launch_bounds__(256) k_einsum(const float* __restrict__ eigvec) {
    int l = blockIdx.y;
    int v0 = blockIdx.x*512 + threadIdx.x*2;
    __shared__ float evs[FF][EE];
    for (int idx = threadIdx.x; idx < FF*EE; idx += 256) {
        int f = idx >> 10, e = idx & 1023;
        float y = g_yout[f*NSAMP + l*EE + e];
        evs[f][e] = fmaxf(fmaf(y, g_sclO[f], g_shfO[f]), 0.f);
    }
    __syncthreads();
    float2 acc[FF];
    #pragma unroll
    for (int f = 0; f < FF; f++) acc[f] = make_float2(0.f, 0.f);
    const float* base = eigvec + ((size_t)l*EE)*VV + v0;
    #pragma unroll 4
    for (int e = 0; e < EE; e++) {
        float2 wv = *(const float2*)(base + (size_t)e*VV);
        #pragma unroll
        for (int f = 0; f < FF; f++) {
            float ev = evs[f][e];
            acc[f].x = fmaf(ev, wv.x, acc[f].x);
            acc[f].y = fmaf(ev, wv.y, acc[f].y);
        }
    }
    #pragma unroll
    for (int f = 0; f < FF; f++)
        *(float2*)&g_fv[((size_t)l*FF + f)*VV + v0] = acc[f];
}

// -------------------- gather + project + register-bitonic sort + signature ------
__global__ void __launch_bounds__(256) k_sig(const int* __restrict__ dgm0,
                                             const int* __restrict__ dgm1rel,
                                             const int* __restrict__ dgm1ext,
                                             const float* __restrict__ Wp,
                                             const float* __restrict__ bp) {
    int bid = blockIdx.x;
    int which = bid & 1;
    int row = bid >> 1;
    int tid = threadIdx.x;
    __shared__ float vals[640];
    __shared__ float srows[7*512];
    __shared__ float s_w0[7], s_w1[7], s_b[7];
    const float* fvr = g_fv + (size_t)row*VV;
    if (tid < 7) { s_w0[tid] = Wp[tid*2]; s_w1[tid] = Wp[tid*2+1]; s_b[tid] = bp[tid]; }
    for (int t = tid; t < 640; t += 256) {
        int src;
        if (which)        src = dgm1ext[row*640 + t];
        else if (t < 512) src = dgm0[row*512 + t];
        else              src = dgm1rel[row*129 + (128 - (t - 512))];
        vals[t] = fvr[src];
    }
    __syncthreads();

    int w = tid >> 5, lane = tid & 31;
    if (w < 7) {
        // element i = r*32 + lane, 16 regs/lane; project directly into registers
        const float PINF = __int_as_float(0x7f800000);
        float w0 = s_w0[w], w1 = s_w1[w], bb = s_b[w];
        float v[16];
        #pragma unroll
        for (int r = 0; r < 16; r++) {
            int i = r*32 + lane;
            v[r] = (i < 320) ? fmaf(vals[2*i], w0, fmaf(vals[2*i+1], w1, bb)) : PINF;
        }
        // bitonic sort, ascending; distances >=32 are register pairs, <32 are shfl
        #pragma unroll
        for (int k = 2; k <= 512; k <<= 1) {
            #pragma unroll
            for (int j = k >> 1; j > 0; j >>= 1) {
                if (j >= 32) {
                    int jr = j >> 5;
                    #pragma unroll
                    for (int r = 0; r < 16; r++) {
                        if ((r & jr) == 0) {
                            int r2 = r | jr;
                            bool dir = ((r & (k >> 5)) == 0);   // k > j >= 32 ⇒ k-bit lives in r
                            float a = v[r], b2 = v[r2];
                            float mn = fminf(a, b2), mx = fmaxf(a, b2);
                            v[r]  = dir ? mn : mx;
                            v[r2] = dir ? mx : mn;
                        }
                    }
                } else {
                    #pragma unroll
                    for (int r = 0; r < 16; r++) {
                        bool dir = (k >= 32) ? ((r & (k >> 5)) == 0)
                                             : ((lane & k) == 0);
                        float b2 = __shfl_xor_sync(0xffffffffu, v[r], j);
                        bool lower = (lane & j) == 0;
                        v[r] = ((dir == lower) ? fminf(v[r], b2) : fmaxf(v[r], b2));
                    }
                }
            }
        }
        #pragma unroll
        for (int r = 0; r < 16; r++) srows[w*512 + r*32 + lane] = v[r];
    }
    __syncthreads();

    if (tid < 64) {
        int i = tid >> 3, j = tid & 7;
        float s1i = 0.f, s2ij = 0.f;
        float s3[8];
        #pragma unroll
        for (int kk = 0; kk < 8; kk++) s3[kk] = 0.f;
        float cur[7];
        #pragma unroll
        for (int d = 0; d < 7; d++) cur[d] = srows[d*512];
        float dx[8];
        dx[0] = DTT;
        for (int p = 0; p < 319; p++) {
            #pragma unroll
            for (int d = 0; d < 7; d++) {
                float nx = srows[d*512 + p + 1];
                dx[d+1] = nx - cur[d];
                cur[d] = nx;
            }
            float dxi = dx[i], dxj = dx[j];
            float c = fmaf(dxj, fmaf(dxi, (1.f/6.f), 0.5f*s1i), s2ij);
            #pragma unroll
            for (int kk = 0; kk < 8; kk++) s3[kk] = fmaf(c, dx[kk], s3[kk]);
            s2ij = fmaf(dxj, fmaf(0.5f, dxi, s1i), s2ij);
            s1i += dxi;
        }
        int l = row >> 3, fi = row & 7;
        float* out = g_x + l*FINALW + fi*(2*SIGLEN) + which*SIGLEN;
        if (j == 0) out[i] = s1i;
        out[8 + tid] = s2ij;
        #pragma unroll
        for (int kk = 0; kk < 8; kk++) out[72 + tid*8 + kk] = s3[kk];
    }
}

// ----------------------- final dot + BatchNorm over L=32 ------------------------
__global__ void k_final(const float* __restrict__ Wf, const float* __restrict__ gfin,
                        const float* __restrict__ betafin, float* __restrict__ out) {
    int w = threadIdx.x >> 5, lane = threadIdx.x & 31;
    const float* xr = g_x + w*FINALW;
    float p = 0.f;
    for (int i = lane; i < FINALW; i += 32) p = fmaf(xr[i], Wf[i], p);
    #pragma unroll
    for (int o = 16; o > 0; o >>= 1) p += __shfl_down_sync(0xffffffffu, p, o);
    __shared__ double s_out[32];
    if (lane == 0) s_out[w] = p;
    __syncthreads();
    __shared__ double sm[2];
    if (threadIdx.x == 0) {
        double S = 0.0, Q = 0.0;
        for (int i = 0; i < 32; i++) { S += s_out[i]; Q += s_out[i]*s_out[i]; }
        double mean = S/32.0;
        sm[0] = mean; sm[1] = Q/32.0 - mean*mean;
    }
    __syncthreads();
    if (threadIdx.x < 32) {
        double r = (s_out[threadIdx.x] - sm[0]) / sqrt(sm[1] + (double)EPSB);
        out[threadIdx.x] = (float)(r*(double)gfin[0] + (double)betafin[0]);
    }
}

// --------------------------------- launcher -------------------------------------
extern "C" void kernel_launch(void* const* d_in, const int* in_sizes, int n_in,
                              void* d_out, int out_size) {
    const float* eigenvalues = (const float*)d_in[0];
    const float* eigvec      = (const float*)d_in[1];
    const int*   dgm0        = (const int*)d_in[2];
    const int*   dgm1rel     = (const int*)d_in[3];
    const int*   dgm1ext     = (const int*)d_in[4];
    const float* mlp_Win     = (const float*)d_in[5];
    const float* mlp_gin     = (const float*)d_in[7];
    const float* mlp_betain  = (const float*)d_in[8];
    const float* mlp_Wh      = (const float*)d_in[9];
    const float* mlp_gh      = (const float*)d_in[11];
    const float* mlp_betah   = (const float*)d_in[12];
    const float* mlp_Wout    = (const float*)d_in[13];
    const float* mlp_gout    = (const float*)d_in[15];
    const float* mlp_betaout = (const float*)d_in[16];
    const float* W_proj      = (const float*)d_in[17];
    const float* b_proj      = (const float*)d_in[18];
    const float* W_fin       = (const float*)d_in[19];
    const float* g_fin       = (const float*)d_in[21];
    const float* beta_fin    = (const float*)d_in[22];
    float* out = (float*)d_out;

    k_xstats<<<1, 1024>>>(eigenvalues, mlp_Win, mlp_gin, mlp_betain);
    k_build1<<<8, 128>>>(mlp_Wh);
    k_seg<<<dim3(128, 8), 256>>>(eigenvalues);
    k_cumstats<<<dim3(128, 8), 256>>>(eigenvalues);
    k_bncoef2<<<8, 128>>>(mlp_gh, mlp_betah);
    k_gemm<<<dim3(256, 8), 256>>>(eigenvalues, mlp_Wh);
    k_bncoef3<<<8, 1024>>>(mlp_gh, mlp_betah);
    k_out<<<dim3(64, 8), 256>>>(mlp_Wout);
    k_bnO<<<1, 32>>>(mlp_gout, mlp_betaout);
    k_einsum<<<dim3(4, 32), 256>>>(eigvec);
    k_sig<<<512, 256>>>(dgm0, dgm1rel, dgm1ext, W_proj, b_proj);
    k_final<<<1, 1024>>>(W_fin, g_fin, beta_fin, out);
}

// round 9
// speedup vs baseline: 1.5228x; 1.0053x over previous
#include <cuda_runtime.h>
#include <math.h>
#include <stdint.h>

#define NSAMP 32768
#define FF 8
#define HU 128
#define VV 2048
#define LL 32
#define EE 1024
#define EPSB 1e-5f
#define DTT (1.0f/51360.0f)
#define SIGLEN 584
#define FINALW 9344
#define NSEG 129

typedef unsigned long long u64;

// ---- packed f32x2 helpers (Blackwell) ----
#define FMA2(d, a, b, c) asm("fma.rn.f32x2 %0, %1, %2, %3;" : "=l"(d) : "l"(a), "l"(b), "l"(c))
#define ADD2(d, a, b)    asm("add.rn.f32x2 %0, %1, %2;" : "=l"(d) : "l"(a), "l"(b))
#define PACKDUPF(out, f) asm("mov.b64 %0, {%1, %1};" : "=l"(out) : "f"(f))
#define UNPACKF(lo, hi, v) asm("mov.b64 {%0, %1}, %2;" : "=f"(lo), "=f"(hi) : "l"(v))

// ------------------------- scratch (__device__ globals) -------------------------
__device__ float g_bufB[(size_t)FF*NSAMP*HU];   // layer-3 preacts
__device__ float g_yout[FF*NSAMP];
__device__ float g_cA[FF*HU], g_cB[FF*HU];
__device__ float g_scl3[FF*HU], g_shf3[FF*HU];
__device__ float g_sclO[FF], g_shfO[FF];
__device__ float g_partF[(size_t)FF*256*2*128];
__device__ double g_partO[FF*64*2];
__device__ float g_fv[(size_t)LL*FF*VV];
__device__ float g_x[LL*FINALW];
// piecewise-linear layer-2 machinery
__device__ float g_T[FF][HU];                   // sorted knots
__device__ float g_P[FF][NSEG][HU], g_Q[FF][NSEG][HU];      // Y2 = P*x+Q per segment
__device__ float g_PP[FF][NSEG][HU], g_QQ[FF][NSEG][HU];    // a2 = relu(PP*x+QQ)
__device__ int   g_seg[FF*NSAMP];
__device__ double g_cumC[FF][HU], g_cumX[FF][HU], g_cumXX[FF][HU]; // cumulative F(s)
__device__ double g_totS, g_totQ;               // global Σx, Σx²

// --------------- x batch stats + analytic layer-1 BN coefficients ---------------
__global__ void k_xstats(const float* __restrict__ x, const float* __restrict__ Win,
                         const float* __restrict__ gin, const float* __restrict__ betain) {
    __shared__ double rs[1024], rq[1024];
    __shared__ double sm[2];
    int t = threadIdx.x;
    double s = 0.0, q = 0.0;
    for (int i = t; i < NSAMP; i += 1024) { double v = x[i]; s += v; q += v*v; }
    rs[t] = s; rq[t] = q; __syncthreads();
    for (int o = 512; o > 0; o >>= 1) {
        if (t < o) { rs[t] += rs[t+o]; rq[t] += rq[t+o]; }
        __syncthreads();
    }
    if (t == 0) {
        double mx = rs[0]/(double)NSAMP;
        sm[0] = mx; sm[1] = rq[0]/(double)NSAMP - mx*mx;
        g_totS = rs[0]; g_totQ = rq[0];
    }
    __syncthreads();
    double mx = sm[0], vx = sm[1];
    double w  = Win[t];
    double g  = gin[t];
    double be = betain[t];
    double cA = w * g / sqrt(w*w*vx + (double)EPSB);
    g_cA[t] = (float)cA;
    g_cB[t] = (float)(be - cA*mx);
}

// ---------------- build sorted knots + per-segment (P,Q) via prefix scan --------
__global__ void __launch_bounds__(128) k_build1(const float* __restrict__ Wh) {
    int f = blockIdx.x, tid = threadIdx.x;
    __shared__ float sT[128], s_cA[128], s_cB[128];
    __shared__ int sK[128];
    __shared__ unsigned char s_init[128];
    float ca = g_cA[f*HU + tid], cb = g_cB[f*HU + tid];
    s_cA[tid] = ca; s_cB[tid] = cb;
    float t;
    if (ca == 0.f) t = __int_as_float(0x7f800000);
    else t = -cb/ca;
    sT[tid] = t; sK[tid] = tid;
    s_init[tid] = (ca < 0.f) || (ca == 0.f && cb > 0.f);
    __syncthreads();
    for (int k = 2; k <= 128; k <<= 1) {
        for (int j = k >> 1; j > 0; j >>= 1) {
            int ixj = tid ^ j;
            if (ixj > tid) {
                float a = sT[tid], b = sT[ixj];
                bool up = ((tid & k) == 0);
                if ((a > b) == up) {
                    sT[tid] = b; sT[ixj] = a;
                    int ka = sK[tid]; sK[tid] = sK[ixj]; sK[ixj] = ka;
                }
            }
            __syncthreads();
        }
    }
    g_T[f][tid] = sT[tid];
    const float* W = Wh + (size_t)f*2*HU*HU;
    float p = 0.f, q = 0.f;
    for (int k = 0; k < 128; k++) {
        if (s_init[k]) {
            float w = W[tid*HU + k];
            p = fmaf(w, s_cA[k], p);
            q = fmaf(w, s_cB[k], q);
        }
    }
    g_P[f][0][tid] = p; g_Q[f][0][tid] = q;
    for (int s = 1; s < NSEG; s++) {
        int ks = sK[s-1];
        float cka = s_cA[ks];
        if (cka != 0.f) {
            float w = W[tid*HU + ks];
            float sgn = (cka > 0.f) ? 1.f : -1.f;
            p = fmaf(sgn*w, cka, p);
            q = fmaf(sgn*w, s_cB[ks], q);
        }
        g_P[f][s][tid] = p; g_Q[f][s][tid] = q;
    }
}

// ---------------------------- segment id per sample -----------------------------
__global__ void __launch_bounds__(256) k_seg(const float* __restrict__ x) {
    int f = blockIdx.y;
    __shared__ float sT[128];
    if (threadIdx.x < 128) sT[threadIdx.x] = g_T[f][threadIdx.x];
    __syncthreads();
    int n = blockIdx.x*256 + threadIdx.x;
    float xv = x[n];
    int lo = 0, hi = 128;
    #pragma unroll
    for (int it = 0; it < 7; it++) {
        int mid = (lo + hi) >> 1;
        if (sT[mid] < xv) lo = mid + 1; else hi = mid;
    }
    if (lo < hi && sT[lo] < xv) lo++;
    g_seg[f*NSAMP + n] = lo;
}

// ------- cumulative F(s) = (cnt, Σx, Σx²) over {x ≤ t_s}; x is L2-resident ------
__global__ void __launch_bounds__(256) k_cumstats(const float* __restrict__ x) {
    int s = blockIdx.x, f = blockIdx.y, tid = threadIdx.x;
    float t = g_T[f][s];
    int   c  = 0;
    float s1a = 0.f, s1b = 0.f, s2a = 0.f, s2b = 0.f;
    #pragma unroll 4
    for (int n = tid; n < NSAMP; n += 512) {
        float va = x[n];
        float vb = x[n + 256];
        if (va <= t) { c++; s1a += va; s2a = fmaf(va, va, s2a); }
        if (vb <= t) { c++; s1b += vb; s2b = fmaf(vb, vb, s2b); }
    }
    __shared__ double shC[256], shX[256], shXX[256];
    shC[tid]  = (double)c;
    shX[tid]  = (double)s1a + (double)s1b;
    shXX[tid] = (double)s2a + (double)s2b;
    __syncthreads();
    for (int o = 128; o > 0; o >>= 1) {
        if (tid < o) { shC[tid] += shC[tid+o]; shX[tid] += shX[tid+o]; shXX[tid] += shXX[tid+o]; }
        __syncthreads();
    }
    if (tid == 0) {
        g_cumC[f][s] = shC[0]; g_cumX[f][s] = shX[0]; g_cumXX[f][s] = shXX[0];
    }
}

// --------- layer-2 BN coefs from cumulative aggregates + fused PP/QQ tables -----
__global__ void __launch_bounds__(128) k_bncoef2(const float* __restrict__ gh,
                                                 const float* __restrict__ betah) {
    int f = blockIdx.x, j = threadIdx.x;
    __shared__ double shC[NSEG], shX[NSEG], shXX[NSEG];
    for (int s = j; s < NSEG; s += 128) {
        double c, xs, xx;
        if (s == 0)           { c = g_cumC[f][0];                 xs = g_cumX[f][0];                 xx = g_cumXX[f][0]; }
        else if (s < NSEG-1)  { c = g_cumC[f][s] - g_cumC[f][s-1]; xs = g_cumX[f][s] - g_cumX[f][s-1]; xx = g_cumXX[f][s] - g_cumXX[f][s-1]; }
        else                  { c = (double)NSAMP - g_cumC[f][127]; xs = g_totS - g_cumX[f][127];     xx = g_totQ - g_cumXX[f][127]; }
        shC[s] = c; shX[s] = xs; shXX[s] = xx;
    }
    __syncthreads();
    double S = 0.0, Q2 = 0.0;
    for (int s = 0; s < NSEG; s++) {
        double p = g_P[f][s][j], q = g_Q[f][s][j];
        S  += p*shX[s] + q*shC[s];
        Q2 += p*p*shXX[s] + 2.0*p*q*shX[s] + q*q*shC[s];
    }
    double mean = S/(double)NSAMP;
    double var  = Q2/(double)NSAMP - mean*mean;
    double g  = gh[f*2*HU + j];
    double be = betah[f*2*HU + j];
    double scl = g / sqrt(var + (double)EPSB);
    double shf = be - scl*mean;
    for (int s = 0; s < NSEG; s++) {
        float p = g_P[f][s][j], q = g_Q[f][s][j];
        g_PP[f][s][j] = (float)(scl*(double)p);
        g_QQ[f][s][j] = (float)(scl*(double)q + shf);
    }
}

// ---------------- hidden-layer GEMM (f32x2), A generated in-place ---------------
__global__ void __launch_bounds__(256, 2) k_gemm(const float* __restrict__ x,
                                                 const float* __restrict__ Wh) {
    __shared__ __align__(16) float As[32][132];
    __shared__ __align__(16) float Bs[32][132];
    __shared__ float sx[128];
    __shared__ int ssg[128];

    int f = blockIdx.y, bx = blockIdx.x, m0 = bx * 128, tid = threadIdx.x;
    int tx = tid & 15, ty = tid >> 4;

    if (tid < 128) {
        sx[tid]  = x[m0 + tid];
        ssg[tid] = g_seg[f*NSAMP + m0 + tid];
    }
    __syncthreads();

    const float* W = Wh + ((size_t)f*2 + 1)*HU*HU;
    const float* PPf = &g_PP[f][0][0];
    const float* QQf = &g_QQ[f][0][0];

    u64 acc[8][4];
    #pragma unroll
    for (int r = 0; r < 8; r++)
        #pragma unroll
        for (int c = 0; c < 4; c++) acc[r][c] = 0ull;

    for (int k0 = 0; k0 < HU; k0 += 32) {
        #pragma unroll
        for (int i = 0; i < 16; i++) {
            int idx = tid + i*256;
            int kk = idx & 31, n = idx >> 5;
            int sgn = ssg[n];
            float a = fmaf(PPf[sgn*HU + k0 + kk], sx[n], QQf[sgn*HU + k0 + kk]);
            As[kk][n] = fmaxf(a, 0.f);
            Bs[kk][n] = W[n*HU + k0 + kk];
        }
        __syncthreads();
        #pragma unroll
        for (int kk = 0; kk < 32; kk++) {
            float a[8];
            *(float4*)(a)   = *(const float4*)&As[kk][ty*8];
            *(float4*)(a+4) = *(const float4*)&As[kk][ty*8+4];
            u64 b[4];
            *(ulonglong2*)(b)   = *(const ulonglong2*)&Bs[kk][tx*8];
            *(ulonglong2*)(b+2) = *(const ulonglong2*)&Bs[kk][tx*8+4];
            #pragma unroll
            for (int r = 0; r < 8; r++) {
                u64 a2;
                PACKDUPF(a2, a[r]);
                #pragma unroll
                for (int c = 0; c < 4; c++) FMA2(acc[r][c], a2, b[c], acc[r][c]);
            }
        }
        __syncthreads();
    }

    #pragma unroll
    for (int r = 0; r < 8; r++) {
        size_t base = ((size_t)f*NSAMP + m0 + ty*8 + r)*HU + tx*8;
        ulonglong2 v0; v0.x = acc[r][0]; v0.y = acc[r][1];
        ulonglong2 v1; v1.x = acc[r][2]; v1.y = acc[r][3];
        *(ulonglong2*)&g_bufB[base]   = v0;
        *(ulonglong2*)&g_bufB[base+4] = v1;
    }

    u64 s2[4], q2[4];
    #pragma unroll
    for (int c = 0; c < 4; c++) { s2[c] = 0ull; q2[c] = 0ull; }
    #pragma unroll
    for (int r = 0; r < 8; r++)
        #pragma unroll
        for (int c = 0; c < 4; c++) {
            ADD2(s2[c], s2[c], acc[r][c]);
            FMA2(q2[c], acc[r][c], acc[r][c], q2[c]);
        }
    __syncthreads();
    u64* sh = (u64*)&As[0][0];
    #pragma unroll
    for (int c = 0; c < 4; c++) {
        sh[(ty*16 + tx)*4 + c]        = s2[c];
        sh[1024 + (ty*16 + tx)*4 + c] = q2[c];
    }
    __syncthreads();
    if (tid < 64) {
        int txx = tid >> 2, cpi = tid & 3;
        u64 S = 0ull, Q = 0ull;
        #pragma unroll
        for (int t2 = 0; t2 < 16; t2++) {
            ADD2(S, S, sh[(t2*16 + txx)*4 + cpi]);
            ADD2(Q, Q, sh[1024 + (t2*16 + txx)*4 + cpi]);
        }
        float slo, shi, qlo, qhi;
        UNPACKF(slo, shi, S);
        UNPACKF(qlo, qhi, Q);
        int col = txx*8 + cpi*2;
        float* P = g_partF + (((size_t)f*256 + bx)*2)*128;
        P[col] = slo; P[col+1] = shi;
        P[128+col] = qlo; P[128+col+1] = qhi;
    }
}

// --------------------- BN coefficients from GEMM partials -----------------------
__global__ void k_bncoef3(const float* __restrict__ gh, const float* __restrict__ betah) {
    int f = blockIdx.x;
    int u = threadIdx.x & 127, h = threadIdx.x >> 7;
    double S = 0.0, Q = 0.0;
    #pragma unroll 8
    for (int b = h; b < 256; b += 8) {
        const float* P = g_partF + (((size_t)f*256 + b)*2)*128;
        S += P[u]; Q += P[128+u];
    }
    __shared__ double shS[1024], shQ[1024];
    shS[h*128+u] = S; shQ[h*128+u] = Q;
    __syncthreads();
    if (h == 0) {
        #pragma unroll
        for (int i = 1; i < 8; i++) { S += shS[i*128+u]; Q += shQ[i*128+u]; }
        double mean = S/(double)NSAMP;
        double var  = Q/(double)NSAMP - mean*mean;
        double g  = gh[f*2*HU + HU + u];
        double be = betah[f*2*HU + HU + u];
        double scl = g / sqrt(var + (double)EPSB);
        g_scl3[f*HU+u] = (float)scl;
        g_shf3[f*HU+u] = (float)(be - scl*mean);
    }
}

// ---------------------- output layer: dot + stats -------------------------------
__global__ void __launch_bounds__(256) k_out(const float* __restrict__ Wout) {
    int f = blockIdx.y;
    int w = threadIdx.x >> 5, lane = threadIdx.x & 31;
    __shared__ float s_w[HU], s_scl[HU], s_shf[HU];
    if (threadIdx.x < 128) {
        s_w[threadIdx.x]   = Wout[f*HU + threadIdx.x];
        s_scl[threadIdx.x] = g_scl3[f*HU + threadIdx.x];
        s_shf[threadIdx.x] = g_shf3[f*HU + threadIdx.x];
    }
    __syncthreads();
    int wg = blockIdx.x*8 + w;
    int n0 = wg*64;
    float w0 = s_w[lane*4], w1 = s_w[lane*4+1], w2 = s_w[lane*4+2], w3 = s_w[lane*4+3];
    float c0 = s_scl[lane*4], c1 = s_scl[lane*4+1], c2 = s_scl[lane*4+2], c3 = s_scl[lane*4+3];
    float h0 = s_shf[lane*4], h1 = s_shf[lane*4+1], h2 = s_shf[lane*4+2], h3 = s_shf[lane*4+3];
    double s = 0.0, q = 0.0;
    for (int n = n0; n < n0 + 64; n++) {
        float4 y = *(const float4*)&g_bufB[((size_t)f*NSAMP + n)*HU + lane*4];
        float p = fmaxf(fmaf(y.x, c0, h0), 0.f)*w0 + fmaxf(fmaf(y.y, c1, h1), 0.f)*w1
                + fmaxf(fmaf(y.z, c2, h2), 0.f)*w2 + fmaxf(fmaf(y.w, c3, h3), 0.f)*w3;
        #pragma unroll
        for (int o = 16; o > 0; o >>= 1) p += __shfl_down_sync(0xffffffffu, p, o);
        if (lane == 0) { g_yout[f*NSAMP + n] = p; s += p; q += (double)p*p; }
    }
    __shared__ double sh_s[8], sh_q[8];
    if (lane == 0) { sh_s[w] = s; sh_q[w] = q; }
    __syncthreads();
    if (threadIdx.x == 0) {
        double S = 0.0, Q = 0.0;
        for (int i = 0; i < 8; i++) { S += sh_s[i]; Q += sh_q[i]; }
        g_partO[(f*64 + blockIdx.x)*2 + 0] = S;
        g_partO[(f*64 + blockIdx.x)*2 + 1] = Q;
    }
}

__global__ void k_bnO(const float* __restrict__ gout, const float* __restrict__ betaout) {
    int f = threadIdx.x;
    if (f >= FF) return;
    double S = 0.0, Q = 0.0;
    for (int b = 0; b < 64; b++) { S += g_partO[(f*64+b)*2]; Q += g_partO[(f*64+b)*2+1]; }
    double mean = S/(double)NSAMP;
    double var  = Q/(double)NSAMP - mean*mean;
    double scl = (double)gout[f] / sqrt(var + (double)EPSB);
    g_sclO[f] = (float)scl;
    g_shfO[f] = (float)((double)betaout[f] - scl*mean);
}

// ---------------------- einsum: fv[l][f][v] = sum_e evs * eigvec ----------------
__global__ void __launch_bounds__(256) k_einsum(const float* __restrict__ eigvec) {
    int l = blockIdx.y;
    int v0 = blockIdx.x*512 + threadIdx.x*2;
    __shared__ float evs[FF][EE];
    for (int idx = threadIdx.x; idx < FF*EE; idx += 256) {
        int f = idx >> 10, e = idx & 1023;
        float y = g_yout[f*NSAMP + l*EE + e];
        evs[f][e] = fmaxf(fmaf(y, g_sclO[f], g_shfO[f]), 0.f);
    }
    __syncthreads();
    float2 acc[FF];
    #pragma unroll
    for (int f = 0; f < FF; f++) acc[f] = make_float2(0.f, 0.f);
    const float* base = eigvec + ((size_t)l*EE)*VV + v0;
    #pragma unroll 4
    for (int e = 0; e < EE; e++) {
        float2 wv = *(const float2*)(base + (size_t)e*VV);
        #pragma unroll
        for (int f = 0; f < FF; f++) {
            float ev = evs[f][e];
            acc[f].x = fmaf(ev, wv.x, acc[f].x);
            acc[f].y = fmaf(ev, wv.y, acc[f].y);
        }
    }
    #pragma unroll
    for (int f = 0; f < FF; f++)
        *(float2*)&g_fv[((size_t)l*FF + f)*VV + v0] = acc[f];
}

// ----- gather + project + register-bitonic sort + chunk-parallel Chen scan ------
__global__ void __launch_bounds__(256) k_sig(const int* __restrict__ dgm0,
                                             const int* __restrict__ dgm1rel,
                                             const int* __restrict__ dgm1ext,
                                             const float* __restrict__ Wp,
                                             const float* __restrict__ bp) {
    int bid = blockIdx.x;
    int which = bid & 1;
    int row = bid >> 1;
    int tid = threadIdx.x;
    __shared__ float vals[640];
    __shared__ float srows[7*512];
    __shared__ float sig[4][SIGLEN];
    __shared__ float s_w0[7], s_w1[7], s_b[7];
    const float* fvr = g_fv + (size_t)row*VV;
    if (tid < 7) { s_w0[tid] = Wp[tid*2]; s_w1[tid] = Wp[tid*2+1]; s_b[tid] = bp[tid]; }
    for (int t = tid; t < 640; t += 256) {
        int src;
        if (which)        src = dgm1ext[row*640 + t];
        else if (t < 512) src = dgm0[row*512 + t];
        else              src = dgm1rel[row*129 + (128 - (t - 512))];
        vals[t] = fvr[src];
    }
    __syncthreads();

    int w = tid >> 5, lane = tid & 31;
    if (w < 7) {
        const float PINF = __int_as_float(0x7f800000);
        float w0 = s_w0[w], w1 = s_w1[w], bb = s_b[w];
        float v[16];
        #pragma unroll
        for (int r = 0; r < 16; r++) {
            int i = r*32 + lane;
            v[r] = (i < 320) ? fmaf(vals[2*i], w0, fmaf(vals[2*i+1], w1, bb)) : PINF;
        }
        #pragma unroll
        for (int k = 2; k <= 512; k <<= 1) {
            #pragma unroll
            for (int j = k >> 1; j > 0; j >>= 1) {
                if (j >= 32) {
                    int jr = j >> 5;
                    #pragma unroll
                    for (int r = 0; r < 16; r++) {
                        if ((r & jr) == 0) {
                            int r2 = r | jr;
                            bool dir = ((r & (k >> 5)) == 0);
                            float a = v[r], b2 = v[r2];
                            float mn = fminf(a, b2), mx = fmaxf(a, b2);
                            v[r]  = dir ? mn : mx;
                            v[r2] = dir ? mx : mn;
                        }
                    }
                } else {
                    #pragma unroll
                    for (int r = 0; r < 16; r++) {
                        bool dir = (k >= 32) ? ((r & (k >> 5)) == 0)
                                             : ((lane & k) == 0);
                        float b2 = __shfl_xor_sync(0xffffffffu, v[r], j);
                        bool lower = (lane & j) == 0;
                        v[r] = ((dir == lower) ? fminf(v[r], b2) : fmaxf(v[r], b2));
                    }
                }
            }
        }
        #pragma unroll
        for (int r = 0; r < 16; r++) srows[w*512 + r*32 + lane] = v[r];
    }
    __syncthreads();

    // ---- chunk-parallel Chen: 4 chunks × 64 threads; increments [c*80, end) ----
    {
        int c = tid >> 6, t = tid & 63;
        int i = t >> 3, j = t & 7;
        int start = c*80;
        int end = (c == 3) ? 319 : start + 80;
        float s1i = 0.f, s2ij = 0.f;
        float s3[8];
        #pragma unroll
        for (int kk = 0; kk < 8; kk++) s3[kk] = 0.f;
        float cur[7];
        #pragma unroll
        for (int d = 0; d < 7; d++) cur[d] = srows[d*512 + start];
        float dx[8];
        dx[0] = DTT;
        for (int p = start; p < end; p++) {
            #pragma unroll
            for (int d = 0; d < 7; d++) {
                float nx = srows[d*512 + p + 1];
                dx[d+1] = nx - cur[d];
                cur[d] = nx;
            }
            float dxi = dx[i], dxj = dx[j];
            float cc = fmaf(dxj, fmaf(dxi, (1.f/6.f), 0.5f*s1i), s2ij);
            #pragma unroll
            for (int kk = 0; kk < 8; kk++) s3[kk] = fmaf(cc, dx[kk], s3[kk]);
            s2ij = fmaf(dxj, fmaf(0.5f, dxi, s1i), s2ij);
            s1i += dxi;
        }
        if (j == 0) sig[c][i] = s1i;
        sig[c][8 + t] = s2ij;
        #pragma unroll
        for (int kk = 0; kk < 8; kk++) sig[c][72 + t*8 + kk] = s3[kk];
    }
    __syncthreads();

    // ---- combine stage 1: (0⊗1)->0, (2⊗3)->2, by two 64-thread groups ----
    {
        float r1 = 0.f, r2 = 0.f, r3[8];
        int g = tid >> 6, t = tid & 63, i = t >> 3, j = t & 7;
        if (g < 2) {
            const float* Lf = sig[2*g];
            const float* Rf = sig[2*g + 1];
            float L1i = Lf[i], L2ij = Lf[8 + t];
            r1 = L1i + Rf[i];
            r2 = L2ij + Rf[8 + t] + L1i*Rf[j];
            #pragma unroll
            for (int kk = 0; kk < 8; kk++)
                r3[kk] = Lf[72 + t*8 + kk] + Rf[72 + t*8 + kk]
                       + L1i*Rf[8 + j*8 + kk] + L2ij*Rf[kk];
        }
        __syncthreads();
        if (g < 2) {
            float* D = sig[2*g];
            if (j == 0) D[i] = r1;
            D[8 + t] = r2;
            #pragma unroll
            for (int kk = 0; kk < 8; kk++) D[72 + t*8 + kk] = r3[kk];
        }
    }
    __syncthreads();

    // ---- combine stage 2: (0⊗2) -> final output ----
    if (tid < 64) {
        int t = tid, i = t >> 3, j = t & 7;
        const float* Lf = sig[0];
        const float* Rf = sig[2];
        float L1i = Lf[i], L2ij = Lf[8 + t];
        int l = row >> 3, fi = row & 7;
        float* out = g_x + l*FINALW + fi*(2*SIGLEN) + which*SIGLEN;
        if (j == 0) out[i] = L1i + Rf[i];
        out[8 + t] = L2ij + Rf[8 + t] + L1i*Rf[j];
        #pragma unroll
        for (int kk = 0; kk < 8; kk++)
            out[72 + t*8 + kk] = Lf[72 + t*8 + kk] + Rf[72 + t*8 + kk]
                               + L1i*Rf[8 + j*8 + kk] + L2ij*Rf[kk];
    }
}

// ----------------------- final dot + BatchNorm over L=32 ------------------------
__global__ void k_final(const float* __restrict__ Wf, const float* __restrict__ gfin,
                        const float* __restrict__ betafin, float* __restrict__ out) {
    int w = threadIdx.x >> 5, lane = threadIdx.x & 31;
    const float* xr = g_x + w*FINALW;
    float p = 0.f;
    for (int i = lane; i < FINALW; i += 32) p = fmaf(xr[i], Wf[i], p);
    #pragma unroll
    for (int o = 16; o > 0; o >>= 1) p += __shfl_down_sync(0xffffffffu, p, o);
    __shared__ double s_out[32];
    if (lane == 0) s_out[w] = p;
    __syncthreads();
    __shared__ double sm[2];
    if (threadIdx.x == 0) {
        double S = 0.0, Q = 0.0;
        for (int i = 0; i < 32; i++) { S += s_out[i]; Q += s_out[i]*s_out[i]; }
        double mean = S/32.0;
        sm[0] = mean; sm[1] = Q/32.0 - mean*mean;
    }
    __syncthreads();
    if (threadIdx.x < 32) {
        double r = (s_out[threadIdx.x] - sm[0]) / sqrt(sm[1] + (double)EPSB);
        out[threadIdx.x] = (float)(r*(double)gfin[0] + (double)betafin[0]);
    }
}

// --------------------------------- launcher -------------------------------------
extern "C" void kernel_launch(void* const* d_in, const int* in_sizes, int n_in,
                              void* d_out, int out_size) {
    const float* eigenvalues = (const float*)d_in[0];
    const float* eigvec      = (const float*)d_in[1];
    const int*   dgm0        = (const int*)d_in[2];
    const int*   dgm1rel     = (const int*)d_in[3];
    const int*   dgm1ext     = (const int*)d_in[4];
    const float* mlp_Win     = (const float*)d_in[5];
    const float* mlp_gin     = (const float*)d_in[7];
    const float* mlp_betain  = (const float*)d_in[8];
    const float* mlp_Wh      = (const float*)d_in[9];
    const float* mlp_gh      = (const float*)d_in[11];
    const float* mlp_betah   = (const float*)d_in[12];
    const float* mlp_Wout    = (const float*)d_in[13];
    const float* mlp_gout    = (const float*)d_in[15];
    const float* mlp_betaout = (const float*)d_in[16];
    const float* W_proj      = (const float*)d_in[17];
    const float* b_proj      = (const float*)d_in[18];
    const float* W_fin       = (const float*)d_in[19];
    const float* g_fin       = (const float*)d_in[21];
    const float* beta_fin    = (const float*)d_in[22];
    float* out = (float*)d_out;

    k_xstats<<<1, 1024>>>(eigenvalues, mlp_Win, mlp_gin, mlp_betain);
    k_build1<<<8, 128>>>(mlp_Wh);
    k_seg<<<dim3(128, 8), 256>>>(eigenvalues);
    k_cumstats<<<dim3(128, 8), 256>>>(eigenvalues);
    k_bncoef2<<<8, 128>>>(mlp_gh, mlp_betah);
    k_gemm<<<dim3(256, 8), 256>>>(eigenvalues, mlp_Wh);
    k_bncoef3<<<8, 1024>>>(mlp_gh, mlp_betah);
    k_out<<<dim3(64, 8), 256>>>(mlp_Wout);
    k_bnO<<<1, 32>>>(mlp_gout, mlp_betaout);
    k_einsum<<<dim3(4, 32), 256>>>(eigvec);
    k_sig<<<512, 256>>>(dgm0, dgm1rel, dgm1ext, W_proj, b_proj);
    k_final<<<1, 1024>>>(W_fin, g_fin, beta_fin, out);
}